// round 12
// baseline (speedup 1.0000x reference)
#include <cuda_runtime.h>
#include <math.h>
#include <stdint.h>

// ParallelRNN via warp-level tf32 mma.sync. B=4096,H=256,L=32,I=64.
// R12: ILP experiment — 256 thr / 8 warps, warp tile 64x64 (2x independent
// MMA chains per warp), k16 chunks ring-3, xi precompute kept.

#define DEVI __device__ __forceinline__

static constexpr long long BHL = 4096LL * 256 * 32;
static constexpr long long BLc = 4096LL * 32;

static constexpr size_t HH_ONE = 32 * 65536;
static constexpr size_t II_ONE = 32 * 16384;
static constexpr size_t HH_TOT = 5 * HH_ONE;
static constexpr size_t W_TOT  = HH_TOT + 3 * II_ONE;

__device__ float g_wr[W_TOT];                  // fragment-ordered tf32 weights
__device__ float g_scr[33554432];              // per-warp r/n scratch
__device__ float g_xi[3ULL * 32 * 4096 * 256]; // xi_r / xi_n / xi_z (+bias)

// main smem: A[0,131072) ring 3x16384[131072,180224) mu[180224,180736)
//            wmu[180736,181760)
static constexpr unsigned SMEM_MAIN = 181760;
// xi smem: xm[0,32768) ring 2x32768[32768,98304)
static constexpr unsigned SMEM_XI = 98304;

DEVI unsigned s2u(const void* p) {
    unsigned a;
    asm("{ .reg .u64 t; cvta.to.shared.u64 t, %1; cvt.u32.u64 %0, t; }"
        : "=r"(a) : "l"(p));
    return a;
}
DEVI float sigm(float v) { return __fdividef(1.f, 1.f + __expf(-v)); }
DEVI float tf32r(float v) {
    uint32_t o;
    asm("cvt.rna.tf32.f32 %0, %1;" : "=r"(o) : "f"(v));
    return __uint_as_float(o);
}
DEVI unsigned aswz(int row, int k4) {
    return (unsigned)(((k4 & ~7) | ((k4 ^ row) & 7)) * 16);
}

// ---------- prep: fragment-ordered tf32 weight images (k16 granules) ----------
__global__ void __launch_bounds__(256)
wprep(const float* __restrict__ Whr, const float* __restrict__ Whn,
      const float* __restrict__ Whz, const float* __restrict__ W1,
      const float* __restrict__ W2,  const float* __restrict__ Wir,
      const float* __restrict__ Win, const float* __restrict__ Wiz) {
    const int bid = blockIdx.x, tid = threadIdx.x;
    const float* src;
    float* dst;
    int c;
    if (bid < 2560) {
        int w = bid >> 9, rem = bid & 511, l = rem >> 4;
        c = rem & 15;
        const float* hs[5] = {Whr, Whn, Whz, W1, W2};
        src = hs[w] + (size_t)l * 65536;
        dst = g_wr + (size_t)(w * 32 + l) * 65536 + (size_t)c * 4096;
    } else {
        int e = bid - 2560;
        int w = e >> 7, rem = e & 127, l = rem >> 2;
        c = rem & 3;
        const float* is[3] = {Wir, Win, Wiz};
        src = is[w] + (size_t)l * 16384;
        dst = g_wr + HH_TOT + (size_t)(w * 32 + l) * 16384 + (size_t)c * 4096;
    }
    const int s = tid >> 7, wc = (tid >> 5) & 3, lane = tid & 31;
#pragma unroll
    for (int j4 = 0; j4 < 4; ++j4) {
        float4 v;
        int k0 = c * 16 + s * 8 + (lane & 3);
        int n0 = wc * 64 + (2 * j4) * 8 + (lane >> 2);
        int n1 = n0 + 8;
        v.x = tf32r(src[(size_t)k0 * 256 + n0]);
        v.y = tf32r(src[(size_t)(k0 + 4) * 256 + n0]);
        v.z = tf32r(src[(size_t)k0 * 256 + n1]);
        v.w = tf32r(src[(size_t)(k0 + 4) * 256 + n1]);
        reinterpret_cast<float4*>(dst)[(s * 4 + j4) * 128 + wc * 32 + lane] = v;
    }
}

// ---- xi gemm (512 thr, warp tile 32x64, k32 chunks) — verbatim from R11 ----
template <int RS>
DEVI void gemm_xi(float (&acc)[2][8][4], unsigned aU, const float* __restrict__ W,
                  int nch, unsigned bU, int tid, int lane, int wr, int wc) {
    {
        const char* s = (const char*)W + (size_t)tid * 64;
        unsigned d = bU + (unsigned)tid * 64u;
#pragma unroll
        for (int q = 0; q < 4; ++q)
            asm volatile("cp.async.cg.shared.global [%0], [%1], 16;"
                         :: "r"(d + q * 16u), "l"(s + q * 16));
        asm volatile("cp.async.commit_group;");
    }
    const int lm = lane >> 3, lr = lane & 7;
    const unsigned bfb = (unsigned)(wc * 32 + lane) * 16u;
    for (int c = 0; c < nch; ++c) {
        asm volatile("cp.async.wait_group 0;");
        __syncthreads();
        if (c + 1 < nch) {
            const char* s = (const char*)W + (size_t)(c + 1) * 32768 + (size_t)tid * 64;
            unsigned d = bU + (unsigned)((c + 1) & 1) * 32768u + (unsigned)tid * 64u;
#pragma unroll
            for (int q = 0; q < 4; ++q)
                asm volatile("cp.async.cg.shared.global [%0], [%1], 16;"
                             :: "r"(d + q * 16u), "l"(s + q * 16));
            asm volatile("cp.async.commit_group;");
        }
        const unsigned bb = bU + (unsigned)(c & 1) * 32768u;
#pragma unroll
        for (int h = 0; h < 2; ++h) {
#pragma unroll
            for (int s = 0; s < 2; ++s) {
                uint32_t bf[8][2];
#pragma unroll
                for (int j4 = 0; j4 < 4; ++j4) {
                    uint32_t v0, v1, v2, v3;
                    asm volatile("ld.shared.v4.b32 {%0,%1,%2,%3}, [%4];"
                        : "=r"(v0), "=r"(v1), "=r"(v2), "=r"(v3)
                        : "r"(bb + (unsigned)h * 16384u
                              + (unsigned)(s * 4 + j4) * 2048u + bfb));
                    bf[2 * j4][0] = v0; bf[2 * j4][1] = v1;
                    bf[2 * j4 + 1][0] = v2; bf[2 * j4 + 1][1] = v3;
                }
                uint32_t af[2][4];
#pragma unroll
                for (int i = 0; i < 2; ++i) {
                    int row = wr * 32 + i * 16 + (lm & 1) * 8 + lr;
                    int k4  = c * 8 + h * 4 + s * 2 + (lm >> 1);
                    unsigned ad = aU + (unsigned)row * RS + aswz(row, k4);
                    asm volatile("ldmatrix.sync.aligned.m8n8.x4.shared.b16 "
                                 "{%0,%1,%2,%3}, [%4];"
                        : "=r"(af[i][0]), "=r"(af[i][1]),
                          "=r"(af[i][2]), "=r"(af[i][3])
                        : "r"(ad));
                }
#pragma unroll
                for (int i = 0; i < 2; ++i)
#pragma unroll
                    for (int j = 0; j < 8; ++j)
                        asm volatile(
                            "mma.sync.aligned.m16n8k8.row.col.f32.tf32.tf32.f32 "
                            "{%0,%1,%2,%3}, {%4,%5,%6,%7}, {%8,%9}, {%0,%1,%2,%3};"
                            : "+f"(acc[i][j][0]), "+f"(acc[i][j][1]),
                              "+f"(acc[i][j][2]), "+f"(acc[i][j][3])
                            : "r"(af[i][0]), "r"(af[i][1]),
                              "r"(af[i][2]), "r"(af[i][3]),
                              "r"(bf[j][0]), "r"(bf[j][1]));
            }
        }
    }
    __syncthreads();
}

// ---- main gemm: 256 thr, 8 warps, warp tile 64x64, k16 chunks ring-3 ----
DEVI void gemm_main(float (&acc)[4][8][4], unsigned aU, const float* __restrict__ W,
                    int nch, unsigned bU, int tid, int lane, int wr, int wc) {
#pragma unroll
    for (int p = 0; p < 2; ++p) {
        const char* s = (const char*)W + (size_t)p * 16384 + (size_t)tid * 64;
        unsigned d = bU + (unsigned)p * 16384u + (unsigned)tid * 64u;
#pragma unroll
        for (int q = 0; q < 4; ++q)
            asm volatile("cp.async.cg.shared.global [%0], [%1], 16;"
                         :: "r"(d + q * 16u), "l"(s + q * 16));
        asm volatile("cp.async.commit_group;");
    }
    const int lm = lane >> 3, lr = lane & 7;
    const unsigned bfb = (unsigned)(wc * 32 + lane) * 16u;
    for (int c = 0; c < nch; ++c) {
        asm volatile("cp.async.wait_group 1;");
        __syncthreads();
        if (c + 2 < nch) {
            const char* s = (const char*)W + (size_t)(c + 2) * 16384 + (size_t)tid * 64;
            unsigned d = bU + (unsigned)((c + 2) % 3) * 16384u + (unsigned)tid * 64u;
#pragma unroll
            for (int q = 0; q < 4; ++q)
                asm volatile("cp.async.cg.shared.global [%0], [%1], 16;"
                             :: "r"(d + q * 16u), "l"(s + q * 16));
        }
        asm volatile("cp.async.commit_group;");
        const unsigned bb = bU + (unsigned)(c % 3) * 16384u;
#pragma unroll
        for (int s = 0; s < 2; ++s) {
            uint32_t bf[8][2];
#pragma unroll
            for (int j4 = 0; j4 < 4; ++j4) {
                uint32_t v0, v1, v2, v3;
                asm volatile("ld.shared.v4.b32 {%0,%1,%2,%3}, [%4];"
                    : "=r"(v0), "=r"(v1), "=r"(v2), "=r"(v3)
                    : "r"(bb + (unsigned)(s * 4 + j4) * 2048u + bfb));
                bf[2 * j4][0] = v0; bf[2 * j4][1] = v1;
                bf[2 * j4 + 1][0] = v2; bf[2 * j4 + 1][1] = v3;
            }
            uint32_t af[4][4];
#pragma unroll
            for (int i = 0; i < 4; ++i) {
                int row = wr * 64 + i * 16 + (lm & 1) * 8 + lr;
                int k4  = c * 4 + s * 2 + (lm >> 1);
                unsigned ad = aU + (unsigned)row * 1024u + aswz(row, k4);
                asm volatile("ldmatrix.sync.aligned.m8n8.x4.shared.b16 "
                             "{%0,%1,%2,%3}, [%4];"
                    : "=r"(af[i][0]), "=r"(af[i][1]),
                      "=r"(af[i][2]), "=r"(af[i][3])
                    : "r"(ad));
            }
#pragma unroll
            for (int i = 0; i < 4; ++i)
#pragma unroll
                for (int j = 0; j < 8; ++j)
                    asm volatile(
                        "mma.sync.aligned.m16n8k8.row.col.f32.tf32.tf32.f32 "
                        "{%0,%1,%2,%3}, {%4,%5,%6,%7}, {%8,%9}, {%0,%1,%2,%3};"
                        : "+f"(acc[i][j][0]), "+f"(acc[i][j][1]),
                          "+f"(acc[i][j][2]), "+f"(acc[i][j][3])
                        : "r"(af[i][0]), "r"(af[i][1]),
                          "r"(af[i][2]), "r"(af[i][3]),
                          "r"(bf[j][0]), "r"(bf[j][1]));
        }
    }
    __syncthreads();
}

#define C0J (wc * 64 + j * 8 + 2 * (lane & 3))

// ---------- xi kernel: xi_g = xm @ Wig + big -> g_xi (512 thr) ----------
__global__ void __launch_bounds__(512, 1)
prnn_xi(const float* __restrict__ x, const float* __restrict__ mask,
        const float* __restrict__ bir, const float* __restrict__ bin_,
        const float* __restrict__ biz) {
    extern __shared__ __align__(16) char smem[];
    const unsigned sU = s2u(smem);
    const unsigned xU = sU, bU = sU + 32768u;
    const int tid = threadIdx.x, lane = tid & 31, w = tid >> 5;
    const int wr = w >> 2, wc = w & 3;
    const int l = blockIdx.x & 31, b0 = (blockIdx.x >> 5) * 128;

#pragma unroll
    for (int q = 0; q < 16; ++q) {
        int idx = tid + q * 512, r = idx >> 6, k = idx & 63;
        float v = tf32r(__ldg(x + (size_t)(b0 + r) * 64 + k)
                        * __ldg(mask + k * 32 + l));
        unsigned ad = xU + (unsigned)r * 256u + aswz(r, k >> 2) + (k & 3) * 4u;
        asm volatile("st.shared.f32 [%0], %1;" :: "r"(ad), "f"(v));
    }
    __syncthreads();
    const float* WI = g_wr + HH_TOT;
    const float* bias[3] = {bir, bin_, biz};
    float acc[2][8][4];
#pragma unroll 1
    for (int g = 0; g < 3; ++g) {
#pragma unroll
        for (int i = 0; i < 2; ++i)
#pragma unroll
            for (int j = 0; j < 8; ++j)
#pragma unroll
                for (int q = 0; q < 4; ++q) acc[i][j][q] = 0.f;
        gemm_xi<256>(acc, xU, WI + (size_t)(g * 32 + l) * 16384, 2,
                     bU, tid, lane, wr, wc);
        const float* bb = bias[g] + l * 256;
        float* dst = g_xi + ((size_t)(g * 32 + l) * 4096 + b0) * 256;
#pragma unroll
        for (int i = 0; i < 2; ++i)
#pragma unroll
            for (int j = 0; j < 8; ++j) {
                int c0 = C0J, r0 = wr * 32 + i * 16 + (lane >> 2), r1 = r0 + 8;
                float2 v0, v1;
                v0.x = acc[i][j][0] + __ldg(bb + c0);
                v0.y = acc[i][j][1] + __ldg(bb + c0 + 1);
                v1.x = acc[i][j][2] + __ldg(bb + c0);
                v1.y = acc[i][j][3] + __ldg(bb + c0 + 1);
                *reinterpret_cast<float2*>(dst + (size_t)r0 * 256 + c0) = v0;
                *reinterpret_cast<float2*>(dst + (size_t)r1 * 256 + c0) = v1;
            }
    }
}

// ---------- main kernel: 5 HH GEMMs, 256 thr, warp tile 64x64 ----------
__global__ void __launch_bounds__(256, 1)
prnn_main(const float* __restrict__ hidden,
          const float* __restrict__ bhn, const float* __restrict__ b1,
          const float* __restrict__ b2,  const float* __restrict__ Wmu,
          const float* __restrict__ bmu, const float* __restrict__ log_var,
          float* __restrict__ out) {
    extern __shared__ __align__(16) char smem[];
    const unsigned sU = s2u(smem);
    const unsigned aU = sU, bU = sU + 131072u;
    float* mu_s  = (float*)(smem + 180224);
    float* wmu_s = (float*)(smem + 180736);
    const int tid = threadIdx.x, lane = tid & 31, w = tid >> 5;
    const int wr = w >> 2, wc = w & 3;           // warp grid 2 x 4, tile 64x64
    const int l = blockIdx.x & 31, b0 = (blockIdx.x >> 5) * 128;

    if (tid < 128) mu_s[tid] = 0.f;
    wmu_s[tid] = __ldg(Wmu + l * 256 + tid);

    {   // A <- tf32(h): thread = column tid, 128 rows
        const float* hp = hidden + (size_t)b0 * 8192 + (size_t)tid * 32 + l;
#pragma unroll 4
        for (int r = 0; r < 128; ++r) {
            float v = tf32r(hp[(size_t)r * 8192]);
            unsigned ad = aU + (unsigned)r * 1024u + aswz(r, tid >> 2)
                        + (tid & 3) * 4u;
            asm volatile("st.shared.f32 [%0], %1;" :: "r"(ad), "f"(v));
        }
    }
    __syncthreads();

    float acc[4][8][4];
    float* scr = g_scr + (size_t)blockIdx.x * 32768 + (size_t)w * 4096;
    const float* WH = g_wr;
    const float* xiR = g_xi + ((size_t)(0 * 32 + l) * 4096 + b0) * 256;
    const float* xiN = g_xi + ((size_t)(1 * 32 + l) * 4096 + b0) * 256;
    const float* xiZ = g_xi + ((size_t)(2 * 32 + l) * 4096 + b0) * 256;
#define R0I4 (wr * 64 + i * 16 + (lane >> 2))
#define SCRP(i, j) (scr + ((size_t)((i) * 8 + (j)) * 32 + lane) * 4)
#define ZACC4()                                                               \
    _Pragma("unroll") for (int i = 0; i < 4; ++i)                             \
    _Pragma("unroll") for (int j = 0; j < 8; ++j)                             \
    _Pragma("unroll") for (int q = 0; q < 4; ++q) acc[i][j][q] = 0.f;
#define ACC_INIT4(src)                                                        \
    _Pragma("unroll") for (int i = 0; i < 4; ++i)                             \
    _Pragma("unroll") for (int j = 0; j < 8; ++j) {                           \
        int c0 = C0J, r0 = R0I4;                                              \
        float2 u0 = __ldg((const float2*)((src) + (size_t)r0 * 256 + c0));    \
        float2 u1 = __ldg((const float2*)((src) + (size_t)(r0 + 8) * 256 + c0)); \
        acc[i][j][0] = u0.x; acc[i][j][1] = u0.y;                             \
        acc[i][j][2] = u1.x; acc[i][j][3] = u1.y;                             \
    }

    // seg1: r = sigmoid(xi_r + h@Whr) -> scratch
    ACC_INIT4(xiR);
    gemm_main(acc, aU, WH + (size_t)(0 * 32 + l) * 65536, 16, bU, tid, lane, wr, wc);
#pragma unroll
    for (int i = 0; i < 4; ++i)
#pragma unroll
        for (int j = 0; j < 8; ++j) {
            float4 v;
            v.x = sigm(acc[i][j][0]);
            v.y = sigm(acc[i][j][1]);
            v.z = sigm(acc[i][j][2]);
            v.w = sigm(acc[i][j][3]);
            *reinterpret_cast<float4*>(SCRP(i, j)) = v;
        }
    // seg2: acc = h@Whn; n = tanh(xi_n + r*(acc+bhn)) -> scratch
    ZACC4();
    gemm_main(acc, aU, WH + (size_t)(1 * 32 + l) * 65536, 16, bU, tid, lane, wr, wc);
    {
        const float* bb = bhn + l * 256;
#pragma unroll
        for (int i = 0; i < 4; ++i)
#pragma unroll
            for (int j = 0; j < 8; ++j) {
                int c0 = C0J, r0 = R0I4;
                float4 rv = *reinterpret_cast<const float4*>(SCRP(i, j));
                float2 n0 = __ldg((const float2*)(xiN + (size_t)r0 * 256 + c0));
                float2 n1 = __ldg((const float2*)(xiN + (size_t)(r0 + 8) * 256 + c0));
                float4 v;
                v.x = tanhf(n0.x + rv.x * (acc[i][j][0] + __ldg(bb + c0)));
                v.y = tanhf(n0.y + rv.y * (acc[i][j][1] + __ldg(bb + c0 + 1)));
                v.z = tanhf(n1.x + rv.z * (acc[i][j][2] + __ldg(bb + c0)));
                v.w = tanhf(n1.y + rv.w * (acc[i][j][3] + __ldg(bb + c0 + 1)));
                *reinterpret_cast<float4*>(SCRP(i, j)) = v;
            }
    }
    // seg3: z = sigmoid(xi_z + h@Whz); hnew = n + z*(h-n) -> A (tf32)
    ACC_INIT4(xiZ);
    gemm_main(acc, aU, WH + (size_t)(2 * 32 + l) * 65536, 16, bU, tid, lane, wr, wc);
#pragma unroll
    for (int i = 0; i < 4; ++i)
#pragma unroll
        for (int j = 0; j < 8; ++j) {
            int c0 = C0J, r0 = R0I4, r1 = r0 + 8;
            float4 nv = *reinterpret_cast<const float4*>(SCRP(i, j));
            float zz[4];
            zz[0] = sigm(acc[i][j][0]);
            zz[1] = sigm(acc[i][j][1]);
            zz[2] = sigm(acc[i][j][2]);
            zz[3] = sigm(acc[i][j][3]);
            const int rr[4] = {r0, r0, r1, r1};
            const int cc[4] = {c0, c0 + 1, c0, c0 + 1};
            const float nn[4] = {nv.x, nv.y, nv.z, nv.w};
#pragma unroll
            for (int q = 0; q < 4; ++q) {
                unsigned ad = aU + (unsigned)rr[q] * 1024u
                            + aswz(rr[q], cc[q] >> 2) + (cc[q] & 3) * 4u;
                float h;
                asm volatile("ld.shared.f32 %0, [%1];" : "=f"(h) : "r"(ad));
                float hv = tf32r(nn[q] + zz[q] * (h - nn[q]));
                asm volatile("st.shared.f32 [%0], %1;" :: "r"(ad), "f"(hv));
            }
        }
    __syncthreads();
    // seg4: h1 = relu(hnew@W1 + b1) -> A (tf32)
    ZACC4();
    gemm_main(acc, aU, WH + (size_t)(3 * 32 + l) * 65536, 16, bU, tid, lane, wr, wc);
    {
        const float* bb = b1 + l * 256;
#pragma unroll
        for (int i = 0; i < 4; ++i)
#pragma unroll
            for (int j = 0; j < 8; ++j) {
                int c0 = C0J, r0 = R0I4, r1 = r0 + 8;
                const int rr[4] = {r0, r0, r1, r1};
                const int cc[4] = {c0, c0 + 1, c0, c0 + 1};
#pragma unroll
                for (int q = 0; q < 4; ++q) {
                    float hv = tf32r(fmaxf(acc[i][j][q] + __ldg(bb + cc[q]), 0.f));
                    unsigned ad = aU + (unsigned)rr[q] * 1024u
                                + aswz(rr[q], cc[q] >> 2) + (cc[q] & 3) * 4u;
                    asm volatile("st.shared.f32 [%0], %1;" :: "r"(ad), "f"(hv));
                }
            }
    }
    __syncthreads();
    // seg5: h2 = relu(h1@W2 + b2) -> out + mu
    ZACC4();
    gemm_main(acc, aU, WH + (size_t)(4 * 32 + l) * 65536, 16, bU, tid, lane, wr, wc);
    {
        const float* bb = b2 + l * 256;
        float mup[4][2];
#pragma unroll
        for (int i = 0; i < 4; ++i) { mup[i][0] = 0.f; mup[i][1] = 0.f; }
#pragma unroll
        for (int i = 0; i < 4; ++i)
#pragma unroll
            for (int j = 0; j < 8; ++j) {
                int c0 = C0J, r0 = R0I4, r1 = r0 + 8;
                float h2a = fmaxf(acc[i][j][0] + __ldg(bb + c0), 0.f);
                float h2b = fmaxf(acc[i][j][1] + __ldg(bb + c0 + 1), 0.f);
                float h2c = fmaxf(acc[i][j][2] + __ldg(bb + c0), 0.f);
                float h2d = fmaxf(acc[i][j][3] + __ldg(bb + c0 + 1), 0.f);
                size_t ob  = (size_t)(b0 + r0) * 8192 + l;
                size_t ob1 = (size_t)(b0 + r1) * 8192 + l;
                out[ob + (size_t)c0 * 32]        = h2a;
                out[ob + (size_t)(c0 + 1) * 32]  = h2b;
                out[ob1 + (size_t)c0 * 32]       = h2c;
                out[ob1 + (size_t)(c0 + 1) * 32] = h2d;
                mup[i][0] += h2a * wmu_s[c0] + h2b * wmu_s[c0 + 1];
                mup[i][1] += h2c * wmu_s[c0] + h2d * wmu_s[c0 + 1];
            }
#pragma unroll
        for (int i = 0; i < 4; ++i)
#pragma unroll
            for (int hq = 0; hq < 2; ++hq) {
                float v = mup[i][hq];
                v += __shfl_xor_sync(0xffffffffu, v, 1);
                v += __shfl_xor_sync(0xffffffffu, v, 2);
                if ((lane & 3) == 0)
                    atomicAdd(&mu_s[wr * 64 + i * 16 + (lane >> 2) + hq * 8], v);
            }
    }
    __syncthreads();
    if (tid < 128) {
        out[BHL + (size_t)(b0 + tid) * 32 + l] = mu_s[tid] + __ldg(bmu + l);
        out[BHL + BLc + (size_t)(b0 + tid) * 32 + l] =
            fmaxf(__ldg(log_var + l), -3.0f);
    }
}

extern "C" void kernel_launch(void* const* d_in, const int* in_sizes, int n_in,
                              void* d_out, int out_size) {
    const float* hidden  = (const float*)d_in[0];
    const float* x       = (const float*)d_in[1];
    const float* mask    = (const float*)d_in[2];
    const float* Wir     = (const float*)d_in[3];
    const float* bir     = (const float*)d_in[4];
    const float* Wiz     = (const float*)d_in[5];
    const float* biz     = (const float*)d_in[6];
    const float* Win     = (const float*)d_in[7];
    const float* bin_    = (const float*)d_in[8];
    const float* Whr     = (const float*)d_in[9];
    const float* Whz     = (const float*)d_in[10];
    const float* Whn     = (const float*)d_in[11];
    const float* bhn     = (const float*)d_in[12];
    const float* W1      = (const float*)d_in[13];
    const float* b1      = (const float*)d_in[14];
    const float* W2      = (const float*)d_in[15];
    const float* b2      = (const float*)d_in[16];
    const float* Wmu     = (const float*)d_in[17];
    const float* bmu     = (const float*)d_in[18];
    const float* log_var = (const float*)d_in[19];
    float* out = (float*)d_out;

    cudaFuncSetAttribute(prnn_xi, cudaFuncAttributeMaxDynamicSharedMemorySize,
                         SMEM_XI);
    cudaFuncSetAttribute(prnn_main, cudaFuncAttributeMaxDynamicSharedMemorySize,
                         SMEM_MAIN);
    wprep<<<2944, 256>>>(Whr, Whn, Whz, W1, W2, Wir, Win, Wiz);
    prnn_xi<<<1024, 512, SMEM_XI>>>(x, mask, bir, bin_, biz);
    prnn_main<<<1024, 256, SMEM_MAIN>>>(hidden, bhn, b1, b2, Wmu, bmu,
                                        log_var, out);
}

// round 13
// speedup vs baseline: 1.0606x; 1.0606x over previous
#include <cuda_runtime.h>
#include <math.h>
#include <stdint.h>

// ParallelRNN via warp-level tf32 mma.sync. B=4096,H=256,L=32,I=64.
// R13: single fused 92-chunk B-stream (no per-segment fills/drains),
// ring-4 lookahead-2 cp.async, inlined epilogues, fast tanh.
// 512 thr, warp grid 4x4, warp tile 32x64, k16 chunks.

#define DEVI __device__ __forceinline__

static constexpr long long BHL = 4096LL * 256 * 32;
static constexpr long long BLc = 4096LL * 32;

static constexpr size_t HH_ONE = 32 * 65536;
static constexpr size_t II_ONE = 32 * 16384;
static constexpr size_t HH_TOT = 5 * HH_ONE;
static constexpr size_t W_TOT  = HH_TOT + 3 * II_ONE;

__device__ float g_wr[W_TOT];        // fragment-ordered tf32 weights (~48MB)
__device__ float g_scr[33554432];    // per-warp r/n scratch

// smem: A[0,131072) xm[131072,163840) ring 4x16384[163840,229376)
//       mu[229376,229888) wmu[229888,230912)
static constexpr unsigned SMEM_BYTES = 230912;

DEVI unsigned s2u(const void* p) {
    unsigned a;
    asm("{ .reg .u64 t; cvta.to.shared.u64 t, %1; cvt.u32.u64 %0, t; }"
        : "=r"(a) : "l"(p));
    return a;
}
DEVI float sigm(float v) { return __fdividef(1.f, 1.f + __expf(-v)); }
DEVI float ftanh(float x) {
    float t = __expf(-2.f * fabsf(x));
    float r = __fdividef(1.f - t, 1.f + t);
    return copysignf(r, x);
}
DEVI float tf32r(float v) {
    uint32_t o;
    asm("cvt.rna.tf32.f32 %0, %1;" : "=r"(o) : "f"(v));
    return __uint_as_float(o);
}
DEVI unsigned aswz(int row, int k4) {
    return (unsigned)(((k4 & ~7) | ((k4 ^ row) & 7)) * 16);
}

// ---------- prep: fragment-ordered tf32 weight images (k16 granules) ----------
__global__ void __launch_bounds__(256)
wprep(const float* __restrict__ Whr, const float* __restrict__ Whn,
      const float* __restrict__ Whz, const float* __restrict__ W1,
      const float* __restrict__ W2,  const float* __restrict__ Wir,
      const float* __restrict__ Win, const float* __restrict__ Wiz) {
    const int bid = blockIdx.x, tid = threadIdx.x;
    const float* src;
    float* dst;
    int c;
    if (bid < 2560) {
        int w = bid >> 9, rem = bid & 511, l = rem >> 4;
        c = rem & 15;
        const float* hs[5] = {Whr, Whn, Whz, W1, W2};
        src = hs[w] + (size_t)l * 65536;
        dst = g_wr + (size_t)(w * 32 + l) * 65536 + (size_t)c * 4096;
    } else {
        int e = bid - 2560;
        int w = e >> 7, rem = e & 127, l = rem >> 2;
        c = rem & 3;
        const float* is[3] = {Wir, Win, Wiz};
        src = is[w] + (size_t)l * 16384;
        dst = g_wr + HH_TOT + (size_t)(w * 32 + l) * 16384 + (size_t)c * 4096;
    }
    const int s = tid >> 7, wc = (tid >> 5) & 3, lane = tid & 31;
#pragma unroll
    for (int j4 = 0; j4 < 4; ++j4) {
        float4 v;
        int k0 = c * 16 + s * 8 + (lane & 3);
        int n0 = wc * 64 + (2 * j4) * 8 + (lane >> 2);
        int n1 = n0 + 8;
        v.x = tf32r(src[(size_t)k0 * 256 + n0]);
        v.y = tf32r(src[(size_t)(k0 + 4) * 256 + n0]);
        v.z = tf32r(src[(size_t)k0 * 256 + n1]);
        v.w = tf32r(src[(size_t)(k0 + 4) * 256 + n1]);
        reinterpret_cast<float4*>(dst)[(s * 4 + j4) * 128 + wc * 32 + lane] = v;
    }
}

// fused stream chunk map: [0,16)Whr [16,20)Wir [20,36)Whn [36,40)Win
//                         [40,56)Whz [56,60)Wiz [60,76)W1 [76,92)W2
DEVI const float* wsrc(int g, int l) {
    const float* WH = g_wr;
    const float* WI = g_wr + HH_TOT;
    if (g < 16) return WH + (size_t)(0 * 32 + l) * 65536 + (size_t)g * 4096;
    if (g < 20) return WI + (size_t)(0 * 32 + l) * 16384 + (size_t)(g - 16) * 4096;
    if (g < 36) return WH + (size_t)(1 * 32 + l) * 65536 + (size_t)(g - 20) * 4096;
    if (g < 40) return WI + (size_t)(1 * 32 + l) * 16384 + (size_t)(g - 36) * 4096;
    if (g < 56) return WH + (size_t)(2 * 32 + l) * 65536 + (size_t)(g - 40) * 4096;
    if (g < 60) return WI + (size_t)(2 * 32 + l) * 16384 + (size_t)(g - 56) * 4096;
    if (g < 76) return WH + (size_t)(3 * 32 + l) * 65536 + (size_t)(g - 60) * 4096;
    return      WH + (size_t)(4 * 32 + l) * 65536 + (size_t)(g - 76) * 4096;
}
DEVI void asrc(int g, unsigned aU, unsigned xU,
               unsigned& base, unsigned& rs, int& kc) {
    if (g < 16)      { base = aU; rs = 1024; kc = g; }
    else if (g < 20) { base = xU; rs = 256;  kc = g - 16; }
    else if (g < 36) { base = aU; rs = 1024; kc = g - 20; }
    else if (g < 40) { base = xU; rs = 256;  kc = g - 36; }
    else if (g < 56) { base = aU; rs = 1024; kc = g - 40; }
    else if (g < 60) { base = xU; rs = 256;  kc = g - 56; }
    else if (g < 76) { base = aU; rs = 1024; kc = g - 60; }
    else             { base = aU; rs = 1024; kc = g - 76; }
}

DEVI void prefetch(const float* __restrict__ W, unsigned dslot, int tid) {
    const char* s = (const char*)W + (size_t)tid * 32;
    unsigned d = dslot + (unsigned)tid * 32u;
    asm volatile("cp.async.cg.shared.global [%0], [%1], 16;" :: "r"(d), "l"(s));
    asm volatile("cp.async.cg.shared.global [%0], [%1], 16;"
                 :: "r"(d + 16u), "l"(s + 16));
}

#define C0J (wc * 64 + j * 8 + 2 * (lane & 3))
#define R0I (wr * 32 + i * 16 + (lane >> 2))

__global__ void __launch_bounds__(512, 1)
prnn_mma(const float* __restrict__ hidden, const float* __restrict__ x,
         const float* __restrict__ mask,
         const float* __restrict__ bir, const float* __restrict__ biz,
         const float* __restrict__ bin_, const float* __restrict__ bhn,
         const float* __restrict__ b1,  const float* __restrict__ b2,
         const float* __restrict__ Wmu, const float* __restrict__ bmu,
         const float* __restrict__ log_var, float* __restrict__ out) {
    extern __shared__ __align__(16) char smem[];
    const unsigned sU = s2u(smem);
    const unsigned aU = sU, xU = sU + 131072u, bU = sU + 163840u;
    float* mu_s  = (float*)(smem + 229376);
    float* wmu_s = (float*)(smem + 229888);
    const int tid = threadIdx.x, lane = tid & 31, w = tid >> 5;
    const int wr = w >> 2, wc = w & 3;           // warp grid 4 x 4
    const int l = blockIdx.x & 31, b0 = (blockIdx.x >> 5) * 128;

    if (tid < 128) mu_s[tid] = 0.f;
    if (tid < 256) wmu_s[tid] = __ldg(Wmu + l * 256 + tid);

    {   // A <- tf32(h): thread = (col, row-half), scattered gmem
        const int colA = tid & 255, rh = tid >> 8;
        const float* hp = hidden + (size_t)(b0 + rh * 64) * 8192
                        + (size_t)colA * 32 + l;
#pragma unroll 4
        for (int r = 0; r < 64; ++r) {
            float v = tf32r(hp[(size_t)r * 8192]);
            int row = rh * 64 + r;
            unsigned ad = aU + (unsigned)row * 1024u + aswz(row, colA >> 2)
                        + (colA & 3) * 4u;
            asm volatile("st.shared.f32 [%0], %1;" :: "r"(ad), "f"(v));
        }
    }
    {   // xm <- tf32(x * mask)
#pragma unroll
        for (int q = 0; q < 16; ++q) {
            int idx = tid + q * 512, r = idx >> 6, k = idx & 63;
            float v = tf32r(__ldg(x + (size_t)(b0 + r) * 64 + k)
                            * __ldg(mask + k * 32 + l));
            unsigned ad = xU + (unsigned)r * 256u + aswz(r, k >> 2) + (k & 3) * 4u;
            asm volatile("st.shared.f32 [%0], %1;" :: "r"(ad), "f"(v));
        }
    }

    float acc[2][8][4];
#pragma unroll
    for (int i = 0; i < 2; ++i)
#pragma unroll
        for (int j = 0; j < 8; ++j)
#pragma unroll
            for (int q = 0; q < 4; ++q) acc[i][j][q] = 0.f;

    float* scr = g_scr + (size_t)blockIdx.x * 32768 + (size_t)w * 2048;
#define SCRP(i, j) (scr + ((size_t)((i) * 8 + (j)) * 32 + lane) * 4)

    // ---- fused pipeline: prologue (chunks 0..2 -> slots 0..2) ----
#pragma unroll
    for (int p = 0; p < 3; ++p) {
        prefetch(wsrc(p, l), bU + (unsigned)p * 16384u, tid);
        asm volatile("cp.async.commit_group;");
    }

    const int lm = lane >> 3, lr = lane & 7;
    const unsigned bfb = (unsigned)(wc * 32 + lane) * 16u;

#pragma unroll 1
    for (int g = 0; g < 92; ++g) {
        asm volatile("cp.async.wait_group 2;");
        __syncthreads();
        if (g + 3 < 92)
            prefetch(wsrc(g + 3, l), bU + (unsigned)((g + 3) & 3) * 16384u, tid);
        asm volatile("cp.async.commit_group;");

        unsigned abase, rs;
        int kc;
        asrc(g, aU, xU, abase, rs, kc);
        const unsigned bb = bU + (unsigned)(g & 3) * 16384u;
#pragma unroll
        for (int s = 0; s < 2; ++s) {
            uint32_t bf[8][2];
#pragma unroll
            for (int j4 = 0; j4 < 4; ++j4) {
                uint32_t v0, v1, v2, v3;
                asm volatile("ld.shared.v4.b32 {%0,%1,%2,%3}, [%4];"
                    : "=r"(v0), "=r"(v1), "=r"(v2), "=r"(v3)
                    : "r"(bb + (unsigned)(s * 4 + j4) * 2048u + bfb));
                bf[2 * j4][0] = v0; bf[2 * j4][1] = v1;
                bf[2 * j4 + 1][0] = v2; bf[2 * j4 + 1][1] = v3;
            }
            uint32_t af[2][4];
#pragma unroll
            for (int i = 0; i < 2; ++i) {
                int row = wr * 32 + i * 16 + (lm & 1) * 8 + lr;
                int k4  = kc * 4 + s * 2 + (lm >> 1);
                unsigned ad = abase + (unsigned)row * rs + aswz(row, k4);
                asm volatile("ldmatrix.sync.aligned.m8n8.x4.shared.b16 "
                             "{%0,%1,%2,%3}, [%4];"
                    : "=r"(af[i][0]), "=r"(af[i][1]),
                      "=r"(af[i][2]), "=r"(af[i][3])
                    : "r"(ad));
            }
#pragma unroll
            for (int i = 0; i < 2; ++i)
#pragma unroll
                for (int j = 0; j < 8; ++j)
                    asm volatile(
                        "mma.sync.aligned.m16n8k8.row.col.f32.tf32.tf32.f32 "
                        "{%0,%1,%2,%3}, {%4,%5,%6,%7}, {%8,%9}, {%0,%1,%2,%3};"
                        : "+f"(acc[i][j][0]), "+f"(acc[i][j][1]),
                          "+f"(acc[i][j][2]), "+f"(acc[i][j][3])
                        : "r"(af[i][0]), "r"(af[i][1]),
                          "r"(af[i][2]), "r"(af[i][3]),
                          "r"(bf[j][0]), "r"(bf[j][1]));
        }

        // ---- inlined epilogues (register / warp-private smem only) ----
        if (g == 19) {          // r = sigmoid(acc + bir) -> scratch; acc = 0
            const float* bb2 = bir + l * 256;
#pragma unroll
            for (int i = 0; i < 2; ++i)
#pragma unroll
                for (int j = 0; j < 8; ++j) {
                    int c0 = C0J;
                    float4 v;
                    v.x = sigm(acc[i][j][0] + __ldg(bb2 + c0));
                    v.y = sigm(acc[i][j][1] + __ldg(bb2 + c0 + 1));
                    v.z = sigm(acc[i][j][2] + __ldg(bb2 + c0));
                    v.w = sigm(acc[i][j][3] + __ldg(bb2 + c0 + 1));
                    *reinterpret_cast<float4*>(SCRP(i, j)) = v;
                    acc[i][j][0] = acc[i][j][1] = acc[i][j][2] = acc[i][j][3] = 0.f;
                }
        } else if (g == 35) {   // acc = r * (acc + bhn)   (continue with Win)
            const float* bb2 = bhn + l * 256;
#pragma unroll
            for (int i = 0; i < 2; ++i)
#pragma unroll
                for (int j = 0; j < 8; ++j) {
                    int c0 = C0J;
                    float4 rv = *reinterpret_cast<const float4*>(SCRP(i, j));
                    acc[i][j][0] = rv.x * (acc[i][j][0] + __ldg(bb2 + c0));
                    acc[i][j][1] = rv.y * (acc[i][j][1] + __ldg(bb2 + c0 + 1));
                    acc[i][j][2] = rv.z * (acc[i][j][2] + __ldg(bb2 + c0));
                    acc[i][j][3] = rv.w * (acc[i][j][3] + __ldg(bb2 + c0 + 1));
                }
        } else if (g == 39) {   // n = tanh(acc + bin) -> scratch; acc = 0
            const float* bb2 = bin_ + l * 256;
#pragma unroll
            for (int i = 0; i < 2; ++i)
#pragma unroll
                for (int j = 0; j < 8; ++j) {
                    int c0 = C0J;
                    float4 v;
                    v.x = ftanh(acc[i][j][0] + __ldg(bb2 + c0));
                    v.y = ftanh(acc[i][j][1] + __ldg(bb2 + c0 + 1));
                    v.z = ftanh(acc[i][j][2] + __ldg(bb2 + c0));
                    v.w = ftanh(acc[i][j][3] + __ldg(bb2 + c0 + 1));
                    *reinterpret_cast<float4*>(SCRP(i, j)) = v;
                    acc[i][j][0] = acc[i][j][1] = acc[i][j][2] = acc[i][j][3] = 0.f;
                }
        } else if (g == 59) {   // z = sigm(acc+biz); hnew = n + z*(h-n) -> A
            const float* bb2 = biz + l * 256;
#pragma unroll
            for (int i = 0; i < 2; ++i)
#pragma unroll
                for (int j = 0; j < 8; ++j) {
                    int c0 = C0J, r0 = R0I, r1 = r0 + 8;
                    float4 nv = *reinterpret_cast<const float4*>(SCRP(i, j));
                    float zz[4];
                    zz[0] = sigm(acc[i][j][0] + __ldg(bb2 + c0));
                    zz[1] = sigm(acc[i][j][1] + __ldg(bb2 + c0 + 1));
                    zz[2] = sigm(acc[i][j][2] + __ldg(bb2 + c0));
                    zz[3] = sigm(acc[i][j][3] + __ldg(bb2 + c0 + 1));
                    const int rr[4] = {r0, r0, r1, r1};
                    const int cc[4] = {c0, c0 + 1, c0, c0 + 1};
                    const float nn[4] = {nv.x, nv.y, nv.z, nv.w};
#pragma unroll
                    for (int q = 0; q < 4; ++q) {
                        unsigned ad = aU + (unsigned)rr[q] * 1024u
                                    + aswz(rr[q], cc[q] >> 2) + (cc[q] & 3) * 4u;
                        float h;
                        asm volatile("ld.shared.f32 %0, [%1];" : "=f"(h) : "r"(ad));
                        float hv = tf32r(nn[q] + zz[q] * (h - nn[q]));
                        asm volatile("st.shared.f32 [%0], %1;" :: "r"(ad), "f"(hv));
                        acc[i][j][q] = 0.f;
                    }
                }
            // per-chunk __syncthreads at next iteration publishes A to all warps
        } else if (g == 75) {   // h1 = relu(acc + b1) -> A
            const float* bb2 = b1 + l * 256;
#pragma unroll
            for (int i = 0; i < 2; ++i)
#pragma unroll
                for (int j = 0; j < 8; ++j) {
                    int c0 = C0J, r0 = R0I, r1 = r0 + 8;
                    const int rr[4] = {r0, r0, r1, r1};
                    const int cc[4] = {c0, c0 + 1, c0, c0 + 1};
#pragma unroll
                    for (int q = 0; q < 4; ++q) {
                        float hv = tf32r(fmaxf(acc[i][j][q] + __ldg(bb2 + cc[q]), 0.f));
                        unsigned ad = aU + (unsigned)rr[q] * 1024u
                                    + aswz(rr[q], cc[q] >> 2) + (cc[q] & 3) * 4u;
                        asm volatile("st.shared.f32 [%0], %1;" :: "r"(ad), "f"(hv));
                        acc[i][j][q] = 0.f;
                    }
                }
        }
    }

    // ---- tail: h2 = relu(acc + b2) -> out + mu ----
    {
        const float* bb2 = b2 + l * 256;
        float mup[2][2];
#pragma unroll
        for (int i = 0; i < 2; ++i) { mup[i][0] = 0.f; mup[i][1] = 0.f; }
#pragma unroll
        for (int i = 0; i < 2; ++i)
#pragma unroll
            for (int j = 0; j < 8; ++j) {
                int c0 = C0J, r0 = R0I, r1 = r0 + 8;
                float h2a = fmaxf(acc[i][j][0] + __ldg(bb2 + c0), 0.f);
                float h2b = fmaxf(acc[i][j][1] + __ldg(bb2 + c0 + 1), 0.f);
                float h2c = fmaxf(acc[i][j][2] + __ldg(bb2 + c0), 0.f);
                float h2d = fmaxf(acc[i][j][3] + __ldg(bb2 + c0 + 1), 0.f);
                size_t ob  = (size_t)(b0 + r0) * 8192 + l;
                size_t ob1 = (size_t)(b0 + r1) * 8192 + l;
                out[ob + (size_t)c0 * 32]        = h2a;
                out[ob + (size_t)(c0 + 1) * 32]  = h2b;
                out[ob1 + (size_t)c0 * 32]       = h2c;
                out[ob1 + (size_t)(c0 + 1) * 32] = h2d;
                mup[i][0] += h2a * wmu_s[c0] + h2b * wmu_s[c0 + 1];
                mup[i][1] += h2c * wmu_s[c0] + h2d * wmu_s[c0 + 1];
            }
#pragma unroll
        for (int i = 0; i < 2; ++i)
#pragma unroll
            for (int hq = 0; hq < 2; ++hq) {
                float v = mup[i][hq];
                v += __shfl_xor_sync(0xffffffffu, v, 1);
                v += __shfl_xor_sync(0xffffffffu, v, 2);
                if ((lane & 3) == 0)
                    atomicAdd(&mu_s[wr * 32 + i * 16 + (lane >> 2) + hq * 8], v);
            }
    }
    __syncthreads();
    if (tid < 128) {
        out[BHL + (size_t)(b0 + tid) * 32 + l] = mu_s[tid] + __ldg(bmu + l);
        out[BHL + BLc + (size_t)(b0 + tid) * 32 + l] =
            fmaxf(__ldg(log_var + l), -3.0f);
    }
}

extern "C" void kernel_launch(void* const* d_in, const int* in_sizes, int n_in,
                              void* d_out, int out_size) {
    const float* hidden  = (const float*)d_in[0];
    const float* x       = (const float*)d_in[1];
    const float* mask    = (const float*)d_in[2];
    const float* Wir     = (const float*)d_in[3];
    const float* bir     = (const float*)d_in[4];
    const float* Wiz     = (const float*)d_in[5];
    const float* biz     = (const float*)d_in[6];
    const float* Win     = (const float*)d_in[7];
    const float* bin_    = (const float*)d_in[8];
    const float* Whr     = (const float*)d_in[9];
    const float* Whz     = (const float*)d_in[10];
    const float* Whn     = (const float*)d_in[11];
    const float* bhn     = (const float*)d_in[12];
    const float* W1      = (const float*)d_in[13];
    const float* b1      = (const float*)d_in[14];
    const float* W2      = (const float*)d_in[15];
    const float* b2      = (const float*)d_in[16];
    const float* Wmu     = (const float*)d_in[17];
    const float* bmu     = (const float*)d_in[18];
    const float* log_var = (const float*)d_in[19];
    float* out = (float*)d_out;

    cudaFuncSetAttribute(prnn_mma, cudaFuncAttributeMaxDynamicSharedMemorySize,
                         SMEM_BYTES);
    wprep<<<2944, 256>>>(Whr, Whn, Whz, W1, W2, Wir, Win, Wiz);
    prnn_mma<<<1024, 512, SMEM_BYTES>>>(hidden, x, mask, bir, biz, bin_, bhn,
                                        b1, b2, Wmu, bmu, log_var, out);
}

// round 14
// speedup vs baseline: 1.2321x; 1.1618x over previous
#include <cuda_runtime.h>
#include <math.h>
#include <stdint.h>

// ParallelRNN via warp-level tf32 mma.sync. B=4096,H=256,L=32,I=64.
// R14: mbarrier producer/consumer B-ring (no per-chunk __syncthreads) —
// warps free-run to break the load/MMA phase convoy. Fused 92-chunk stream,
// smem pointer tables, 512 thr, warp tile 32x64, k16 chunks, ring 4.

#define DEVI __device__ __forceinline__

static constexpr long long BHL = 4096LL * 256 * 32;
static constexpr long long BLc = 4096LL * 32;

static constexpr size_t HH_ONE = 32 * 65536;
static constexpr size_t II_ONE = 32 * 16384;
static constexpr size_t HH_TOT = 5 * HH_ONE;
static constexpr size_t W_TOT  = HH_TOT + 3 * II_ONE;

__device__ float g_wr[W_TOT];        // fragment-ordered tf32 weights (~48MB)
__device__ float g_scr[33554432];    // per-warp r/n scratch

// smem: A[0,131072) xm[131072,163840) ring 4x16384[163840,229376)
//       mbars[229376,229440) wptr[229440,230176) aux[230176,230912)
//       mu[230912,231424)
static constexpr unsigned OFF_MB   = 229376;
static constexpr unsigned OFF_WPTR = 229440;
static constexpr unsigned OFF_AUX  = 230176;
static constexpr unsigned OFF_MU   = 230912;
static constexpr unsigned SMEM_BYTES = 231424;

DEVI unsigned s2u(const void* p) {
    unsigned a;
    asm("{ .reg .u64 t; cvta.to.shared.u64 t, %1; cvt.u32.u64 %0, t; }"
        : "=r"(a) : "l"(p));
    return a;
}
DEVI float sigm(float v) { return __fdividef(1.f, 1.f + __expf(-v)); }
DEVI float ftanh(float x) {
    float t = __expf(-2.f * fabsf(x));
    return copysignf(__fdividef(1.f - t, 1.f + t), x);
}
DEVI float tf32r(float v) {
    uint32_t o;
    asm("cvt.rna.tf32.f32 %0, %1;" : "=r"(o) : "f"(v));
    return __uint_as_float(o);
}
DEVI unsigned aswz(int row, int k4) {
    return (unsigned)(((k4 & ~7) | ((k4 ^ row) & 7)) * 16);
}

#define MB_INIT(a, n) \
    asm volatile("mbarrier.init.shared.b64 [%0], %1;" :: "r"(a), "r"(n) : "memory")
#define MB_ARRIVE(a) \
    asm volatile("mbarrier.arrive.release.cta.shared::cta.b64 _, [%0];" \
                 :: "r"(a) : "memory")
#define MB_WAIT(a, p) do {                                                    \
    unsigned _d;                                                              \
    asm volatile("{\n\t.reg .pred P;\n\t"                                     \
        "mbarrier.try_wait.parity.acquire.cta.shared::cta.b64 P, [%1], %2;\n\t" \
        "selp.b32 %0,1,0,P;\n\t}" : "=r"(_d) : "r"(a), "r"(p) : "memory");    \
    if (!_d) {                                                                \
        asm volatile("{\n\t.reg .pred P;\n\tLW%=:\n\t"                        \
            "mbarrier.try_wait.parity.acquire.cta.shared::cta.b64 P, [%0], %1, 0x989680;\n\t" \
            "@P bra LD%=;\n\tbra LW%=;\n\tLD%=:\n\t}"                         \
            :: "r"(a), "r"(p) : "memory");                                    \
    } } while (0)
#define CPA_MB_ARRIVE(a) \
    asm volatile("cp.async.mbarrier.arrive.noinc.shared.b64 [%0];" \
                 :: "r"(a) : "memory")

// ---------- prep: fragment-ordered tf32 weight images (k16 granules) ----------
__global__ void __launch_bounds__(256)
wprep(const float* __restrict__ Whr, const float* __restrict__ Whn,
      const float* __restrict__ Whz, const float* __restrict__ W1,
      const float* __restrict__ W2,  const float* __restrict__ Wir,
      const float* __restrict__ Win, const float* __restrict__ Wiz) {
    const int bid = blockIdx.x, tid = threadIdx.x;
    const float* src;
    float* dst;
    int c;
    if (bid < 2560) {
        int w = bid >> 9, rem = bid & 511, l = rem >> 4;
        c = rem & 15;
        const float* hs[5] = {Whr, Whn, Whz, W1, W2};
        src = hs[w] + (size_t)l * 65536;
        dst = g_wr + (size_t)(w * 32 + l) * 65536 + (size_t)c * 4096;
    } else {
        int e = bid - 2560;
        int w = e >> 7, rem = e & 127, l = rem >> 2;
        c = rem & 3;
        const float* is[3] = {Wir, Win, Wiz};
        src = is[w] + (size_t)l * 16384;
        dst = g_wr + HH_TOT + (size_t)(w * 32 + l) * 16384 + (size_t)c * 4096;
    }
    const int s = tid >> 7, wc = (tid >> 5) & 3, lane = tid & 31;
#pragma unroll
    for (int j4 = 0; j4 < 4; ++j4) {
        float4 v;
        int k0 = c * 16 + s * 8 + (lane & 3);
        int n0 = wc * 64 + (2 * j4) * 8 + (lane >> 2);
        int n1 = n0 + 8;
        v.x = tf32r(src[(size_t)k0 * 256 + n0]);
        v.y = tf32r(src[(size_t)(k0 + 4) * 256 + n0]);
        v.z = tf32r(src[(size_t)k0 * 256 + n1]);
        v.w = tf32r(src[(size_t)(k0 + 4) * 256 + n1]);
        reinterpret_cast<float4*>(dst)[(s * 4 + j4) * 128 + wc * 32 + lane] = v;
    }
}

// fused stream chunk map: [0,16)Whr [16,20)Wir [20,36)Whn [36,40)Win
//                         [40,56)Whz [56,60)Wiz [60,76)W1 [76,92)W2
DEVI const float* wsrc(int g, int l) {
    const float* WH = g_wr;
    const float* WI = g_wr + HH_TOT;
    if (g < 16) return WH + (size_t)(0 * 32 + l) * 65536 + (size_t)g * 4096;
    if (g < 20) return WI + (size_t)(0 * 32 + l) * 16384 + (size_t)(g - 16) * 4096;
    if (g < 36) return WH + (size_t)(1 * 32 + l) * 65536 + (size_t)(g - 20) * 4096;
    if (g < 40) return WI + (size_t)(1 * 32 + l) * 16384 + (size_t)(g - 36) * 4096;
    if (g < 56) return WH + (size_t)(2 * 32 + l) * 65536 + (size_t)(g - 40) * 4096;
    if (g < 60) return WI + (size_t)(2 * 32 + l) * 16384 + (size_t)(g - 56) * 4096;
    if (g < 76) return WH + (size_t)(3 * 32 + l) * 65536 + (size_t)(g - 60) * 4096;
    return      WH + (size_t)(4 * 32 + l) * 65536 + (size_t)(g - 76) * 4096;
}
DEVI void achunk(int g, unsigned& rs, int& kc) {
    if (g < 16)      { rs = 1024; kc = g; }
    else if (g < 20) { rs = 256;  kc = g - 16; }
    else if (g < 36) { rs = 1024; kc = g - 20; }
    else if (g < 40) { rs = 256;  kc = g - 36; }
    else if (g < 56) { rs = 1024; kc = g - 40; }
    else if (g < 60) { rs = 256;  kc = g - 56; }
    else if (g < 76) { rs = 1024; kc = g - 60; }
    else             { rs = 1024; kc = g - 76; }
}

#define C0J (wc * 64 + j * 8 + 2 * (lane & 3))
#define R0I (wr * 32 + i * 16 + (lane >> 2))

__global__ void __launch_bounds__(512, 1)
prnn_mma(const float* __restrict__ hidden, const float* __restrict__ x,
         const float* __restrict__ mask,
         const float* __restrict__ bir, const float* __restrict__ biz,
         const float* __restrict__ bin_, const float* __restrict__ bhn,
         const float* __restrict__ b1,  const float* __restrict__ b2,
         const float* __restrict__ Wmu, const float* __restrict__ bmu,
         const float* __restrict__ log_var, float* __restrict__ out) {
    extern __shared__ __align__(16) char smem[];
    const unsigned sU = s2u(smem);
    const unsigned aU = sU, xU = sU + 131072u, bU = sU + 163840u;
    const unsigned mbU = sU + OFF_MB, wpU = sU + OFF_WPTR, axU = sU + OFF_AUX;
    float* mu_s = (float*)(smem + OFF_MU);
    const int tid = threadIdx.x, lane = tid & 31, w = tid >> 5;
    const int wr = w >> 2, wc = w & 3;           // warp grid 4 x 4
    const int l = blockIdx.x & 31, b0 = (blockIdx.x >> 5) * 128;

    if (tid < 128) mu_s[tid] = 0.f;
    if (tid < 8) MB_INIT(mbU + tid * 8u, tid < 4 ? 512u : 16u);  // full:0-3 empty:4-7
    if (tid < 92) {                                  // pointer + aux tables
        uint64_t wp = (uint64_t)wsrc(tid, l);
        unsigned rs;
        int kc;
        achunk(tid, rs, kc);
        asm volatile("st.shared.u64 [%0], %1;" :: "r"(wpU + tid * 8u), "l"(wp));
        asm volatile("st.shared.v2.u32 [%0], {%1, %2};"
                     :: "r"(axU + tid * 8u), "r"(rs), "r"((unsigned)(kc * 4)));
    }

    {   // A <- tf32(h): thread = (col, row-half), scattered gmem
        const int colA = tid & 255, rh = tid >> 8;
        const float* hp = hidden + (size_t)(b0 + rh * 64) * 8192
                        + (size_t)colA * 32 + l;
#pragma unroll 4
        for (int r = 0; r < 64; ++r) {
            float v = tf32r(hp[(size_t)r * 8192]);
            int row = rh * 64 + r;
            unsigned ad = aU + (unsigned)row * 1024u + aswz(row, colA >> 2)
                        + (colA & 3) * 4u;
            asm volatile("st.shared.f32 [%0], %1;" :: "r"(ad), "f"(v));
        }
    }
    {   // xm <- tf32(x * mask)
#pragma unroll
        for (int q = 0; q < 16; ++q) {
            int idx = tid + q * 512, r = idx >> 6, k = idx & 63;
            float v = tf32r(__ldg(x + (size_t)(b0 + r) * 64 + k)
                            * __ldg(mask + k * 32 + l));
            unsigned ad = xU + (unsigned)r * 256u + aswz(r, k >> 2) + (k & 3) * 4u;
            asm volatile("st.shared.f32 [%0], %1;" :: "r"(ad), "f"(v));
        }
    }
    __syncthreads();   // A, xm, tables, mbarriers all ready

    float acc[2][8][4];
#pragma unroll
    for (int i = 0; i < 2; ++i)
#pragma unroll
        for (int j = 0; j < 8; ++j)
#pragma unroll
            for (int q = 0; q < 4; ++q) acc[i][j][q] = 0.f;

    float* scr = g_scr + (size_t)blockIdx.x * 32768 + (size_t)w * 2048;
#define SCRP(i, j) (scr + ((size_t)((i) * 8 + (j)) * 32 + lane) * 4)

    // ---- prologue: fill slots 0..2 (use 0 of each -> no empty wait) ----
#pragma unroll
    for (int p = 0; p < 3; ++p) {
        uint64_t wp;
        asm volatile("ld.shared.u64 %0, [%1];" : "=l"(wp) : "r"(wpU + p * 8u));
        const char* s = (const char*)wp + (size_t)tid * 32;
        unsigned d = bU + (unsigned)p * 16384u + (unsigned)tid * 32u;
        asm volatile("cp.async.cg.shared.global [%0], [%1], 16;" :: "r"(d), "l"(s));
        asm volatile("cp.async.cg.shared.global [%0], [%1], 16;"
                     :: "r"(d + 16u), "l"(s + 16));
        CPA_MB_ARRIVE(mbU + p * 8u);
    }

    const int lm = lane >> 3, lr = lane & 7;
    const unsigned bfb = (unsigned)(wc * 32 + lane) * 16u;

#pragma unroll 1
    for (int g = 0; g < 92; ++g) {
        // ---- producer: fill chunk g+3 into slot (g+3)&3 ----
        if (g + 3 < 92) {
            int gg = g + 3, s2 = gg & 3, t2 = gg >> 2;
            MB_WAIT(mbU + 32u + (unsigned)s2 * 8u, (unsigned)((t2 & 1) ^ 1));
            uint64_t wp;
            asm volatile("ld.shared.u64 %0, [%1];" : "=l"(wp) : "r"(wpU + gg * 8u));
            const char* s = (const char*)wp + (size_t)tid * 32;
            unsigned d = bU + (unsigned)s2 * 16384u + (unsigned)tid * 32u;
            asm volatile("cp.async.cg.shared.global [%0], [%1], 16;" :: "r"(d), "l"(s));
            asm volatile("cp.async.cg.shared.global [%0], [%1], 16;"
                         :: "r"(d + 16u), "l"(s + 16));
            CPA_MB_ARRIVE(mbU + (unsigned)s2 * 8u);
        }
        // ---- consumer: wait data, compute ----
        const int sl = g & 3;
        MB_WAIT(mbU + (unsigned)sl * 8u, (unsigned)((g >> 2) & 1));

        unsigned rs, k4b;
        asm volatile("ld.shared.v2.u32 {%0, %1}, [%2];"
                     : "=r"(rs), "=r"(k4b) : "r"(axU + g * 8u));
        const unsigned abase = (rs == 256u) ? xU : aU;
        const unsigned bb = bU + (unsigned)sl * 16384u;
#pragma unroll
        for (int s = 0; s < 2; ++s) {
            uint32_t bf[8][2];
#pragma unroll
            for (int j4 = 0; j4 < 4; ++j4) {
                uint32_t v0, v1, v2, v3;
                asm volatile("ld.shared.v4.b32 {%0,%1,%2,%3}, [%4];"
                    : "=r"(v0), "=r"(v1), "=r"(v2), "=r"(v3)
                    : "r"(bb + (unsigned)(s * 4 + j4) * 2048u + bfb));
                bf[2 * j4][0] = v0; bf[2 * j4][1] = v1;
                bf[2 * j4 + 1][0] = v2; bf[2 * j4 + 1][1] = v3;
            }
            uint32_t af[2][4];
#pragma unroll
            for (int i = 0; i < 2; ++i) {
                int row = wr * 32 + i * 16 + (lm & 1) * 8 + lr;
                int k4  = (int)k4b + s * 2 + (lm >> 1);
                unsigned ad = abase + (unsigned)row * rs + aswz(row, k4);
                asm volatile("ldmatrix.sync.aligned.m8n8.x4.shared.b16 "
                             "{%0,%1,%2,%3}, [%4];"
                    : "=r"(af[i][0]), "=r"(af[i][1]),
                      "=r"(af[i][2]), "=r"(af[i][3])
                    : "r"(ad));
            }
#pragma unroll
            for (int i = 0; i < 2; ++i)
#pragma unroll
                for (int j = 0; j < 8; ++j)
                    asm volatile(
                        "mma.sync.aligned.m16n8k8.row.col.f32.tf32.tf32.f32 "
                        "{%0,%1,%2,%3}, {%4,%5,%6,%7}, {%8,%9}, {%0,%1,%2,%3};"
                        : "+f"(acc[i][j][0]), "+f"(acc[i][j][1]),
                          "+f"(acc[i][j][2]), "+f"(acc[i][j][3])
                        : "r"(af[i][0]), "r"(af[i][1]),
                          "r"(af[i][2]), "r"(af[i][3]),
                          "r"(bf[j][0]), "r"(bf[j][1]));
        }
        if (lane == 0) MB_ARRIVE(mbU + 32u + (unsigned)sl * 8u);

        // ---- inlined epilogues ----
        if (g == 19) {          // r = sigmoid(acc + bir) -> scratch; acc = 0
            const float* bb2 = bir + l * 256;
#pragma unroll
            for (int i = 0; i < 2; ++i)
#pragma unroll
                for (int j = 0; j < 8; ++j) {
                    int c0 = C0J;
                    float4 v;
                    v.x = sigm(acc[i][j][0] + __ldg(bb2 + c0));
                    v.y = sigm(acc[i][j][1] + __ldg(bb2 + c0 + 1));
                    v.z = sigm(acc[i][j][2] + __ldg(bb2 + c0));
                    v.w = sigm(acc[i][j][3] + __ldg(bb2 + c0 + 1));
                    *reinterpret_cast<float4*>(SCRP(i, j)) = v;
                    acc[i][j][0] = acc[i][j][1] = acc[i][j][2] = acc[i][j][3] = 0.f;
                }
        } else if (g == 35) {   // acc = r * (acc + bhn)
            const float* bb2 = bhn + l * 256;
#pragma unroll
            for (int i = 0; i < 2; ++i)
#pragma unroll
                for (int j = 0; j < 8; ++j) {
                    int c0 = C0J;
                    float4 rv = *reinterpret_cast<const float4*>(SCRP(i, j));
                    acc[i][j][0] = rv.x * (acc[i][j][0] + __ldg(bb2 + c0));
                    acc[i][j][1] = rv.y * (acc[i][j][1] + __ldg(bb2 + c0 + 1));
                    acc[i][j][2] = rv.z * (acc[i][j][2] + __ldg(bb2 + c0));
                    acc[i][j][3] = rv.w * (acc[i][j][3] + __ldg(bb2 + c0 + 1));
                }
        } else if (g == 39) {   // n = tanh(acc + bin) -> scratch; acc = 0
            const float* bb2 = bin_ + l * 256;
#pragma unroll
            for (int i = 0; i < 2; ++i)
#pragma unroll
                for (int j = 0; j < 8; ++j) {
                    int c0 = C0J;
                    float4 v;
                    v.x = ftanh(acc[i][j][0] + __ldg(bb2 + c0));
                    v.y = ftanh(acc[i][j][1] + __ldg(bb2 + c0 + 1));
                    v.z = ftanh(acc[i][j][2] + __ldg(bb2 + c0));
                    v.w = ftanh(acc[i][j][3] + __ldg(bb2 + c0 + 1));
                    *reinterpret_cast<float4*>(SCRP(i, j)) = v;
                    acc[i][j][0] = acc[i][j][1] = acc[i][j][2] = acc[i][j][3] = 0.f;
                }
        } else if (g == 59) {   // z = sigm(acc+biz); hnew = n + z*(h-n) -> A
            __syncthreads();    // all warps done READING h through chunk 59
            const float* bb2 = biz + l * 256;
#pragma unroll
            for (int i = 0; i < 2; ++i)
#pragma unroll
                for (int j = 0; j < 8; ++j) {
                    int c0 = C0J, r0 = R0I, r1 = r0 + 8;
                    float4 nv = *reinterpret_cast<const float4*>(SCRP(i, j));
                    float zz[4];
                    zz[0] = sigm(acc[i][j][0] + __ldg(bb2 + c0));
                    zz[1] = sigm(acc[i][j][1] + __ldg(bb2 + c0 + 1));
                    zz[2] = sigm(acc[i][j][2] + __ldg(bb2 + c0));
                    zz[3] = sigm(acc[i][j][3] + __ldg(bb2 + c0 + 1));
                    const int rr[4] = {r0, r0, r1, r1};
                    const int cc[4] = {c0, c0 + 1, c0, c0 + 1};
                    const float nn[4] = {nv.x, nv.y, nv.z, nv.w};
#pragma unroll
                    for (int q = 0; q < 4; ++q) {
                        unsigned ad = aU + (unsigned)rr[q] * 1024u
                                    + aswz(rr[q], cc[q] >> 2) + (cc[q] & 3) * 4u;
                        float h;
                        asm volatile("ld.shared.f32 %0, [%1];" : "=f"(h) : "r"(ad));
                        float hv = tf32r(nn[q] + zz[q] * (h - nn[q]));
                        asm volatile("st.shared.f32 [%0], %1;" :: "r"(ad), "f"(hv));
                        acc[i][j][q] = 0.f;
                    }
                }
            __syncthreads();    // hnew visible before anyone reads at g=60
        } else if (g == 75) {   // h1 = relu(acc + b1) -> A
            __syncthreads();
            const float* bb2 = b1 + l * 256;
#pragma unroll
            for (int i = 0; i < 2; ++i)
#pragma unroll
                for (int j = 0; j < 8; ++j) {
                    int c0 = C0J, r0 = R0I, r1 = r0 + 8;
                    const int rr[4] = {r0, r0, r1, r1};
                    const int cc[4] = {c0, c0 + 1, c0, c0 + 1};
#pragma unroll
                    for (int q = 0; q < 4; ++q) {
                        float hv = tf32r(fmaxf(acc[i][j][q] + __ldg(bb2 + cc[q]), 0.f));
                        unsigned ad = aU + (unsigned)rr[q] * 1024u
                                    + aswz(rr[q], cc[q] >> 2) + (cc[q] & 3) * 4u;
                        asm volatile("st.shared.f32 [%0], %1;" :: "r"(ad), "f"(hv));
                        acc[i][j][q] = 0.f;
                    }
                }
            __syncthreads();
        }
    }

    // ---- tail: h2 = relu(acc + b2) -> out + mu ----
    {
        const float* bb2 = b2 + l * 256;
        const float* wml = Wmu + l * 256;
        float mup[2][2];
#pragma unroll
        for (int i = 0; i < 2; ++i) { mup[i][0] = 0.f; mup[i][1] = 0.f; }
#pragma unroll
        for (int i = 0; i < 2; ++i)
#pragma unroll
            for (int j = 0; j < 8; ++j) {
                int c0 = C0J, r0 = R0I, r1 = r0 + 8;
                float h2a = fmaxf(acc[i][j][0] + __ldg(bb2 + c0), 0.f);
                float h2b = fmaxf(acc[i][j][1] + __ldg(bb2 + c0 + 1), 0.f);
                float h2c = fmaxf(acc[i][j][2] + __ldg(bb2 + c0), 0.f);
                float h2d = fmaxf(acc[i][j][3] + __ldg(bb2 + c0 + 1), 0.f);
                size_t ob  = (size_t)(b0 + r0) * 8192 + l;
                size_t ob1 = (size_t)(b0 + r1) * 8192 + l;
                out[ob + (size_t)c0 * 32]        = h2a;
                out[ob + (size_t)(c0 + 1) * 32]  = h2b;
                out[ob1 + (size_t)c0 * 32]       = h2c;
                out[ob1 + (size_t)(c0 + 1) * 32] = h2d;
                mup[i][0] += h2a * __ldg(wml + c0) + h2b * __ldg(wml + c0 + 1);
                mup[i][1] += h2c * __ldg(wml + c0) + h2d * __ldg(wml + c0 + 1);
            }
#pragma unroll
        for (int i = 0; i < 2; ++i)
#pragma unroll
            for (int hq = 0; hq < 2; ++hq) {
                float v = mup[i][hq];
                v += __shfl_xor_sync(0xffffffffu, v, 1);
                v += __shfl_xor_sync(0xffffffffu, v, 2);
                if ((lane & 3) == 0)
                    atomicAdd(&mu_s[wr * 32 + i * 16 + (lane >> 2) + hq * 8], v);
            }
    }
    __syncthreads();
    if (tid < 128) {
        out[BHL + (size_t)(b0 + tid) * 32 + l] = mu_s[tid] + __ldg(bmu + l);
        out[BHL + BLc + (size_t)(b0 + tid) * 32 + l] =
            fmaxf(__ldg(log_var + l), -3.0f);
    }
}

extern "C" void kernel_launch(void* const* d_in, const int* in_sizes, int n_in,
                              void* d_out, int out_size) {
    const float* hidden  = (const float*)d_in[0];
    const float* x       = (const float*)d_in[1];
    const float* mask    = (const float*)d_in[2];
    const float* Wir     = (const float*)d_in[3];
    const float* bir     = (const float*)d_in[4];
    const float* Wiz     = (const float*)d_in[5];
    const float* biz     = (const float*)d_in[6];
    const float* Win     = (const float*)d_in[7];
    const float* bin_    = (const float*)d_in[8];
    const float* Whr     = (const float*)d_in[9];
    const float* Whz     = (const float*)d_in[10];
    const float* Whn     = (const float*)d_in[11];
    const float* bhn     = (const float*)d_in[12];
    const float* W1      = (const float*)d_in[13];
    const float* b1      = (const float*)d_in[14];
    const float* W2      = (const float*)d_in[15];
    const float* b2      = (const float*)d_in[16];
    const float* Wmu     = (const float*)d_in[17];
    const float* bmu     = (const float*)d_in[18];
    const float* log_var = (const float*)d_in[19];
    float* out = (float*)d_out;

    cudaFuncSetAttribute(prnn_mma, cudaFuncAttributeMaxDynamicSharedMemorySize,
                         SMEM_BYTES);
    wprep<<<2944, 256>>>(Whr, Whn, Whz, W1, W2, Wir, Win, Wiz);
    prnn_mma<<<1024, 512, SMEM_BYTES>>>(hidden, x, mask, bir, biz, bin_, bhn,
                                        b1, b2, Wmu, bmu, log_var, out);
}

// round 15
// speedup vs baseline: 1.2739x; 1.0339x over previous
#include <cuda_runtime.h>
#include <math.h>
#include <stdint.h>

// ParallelRNN via warp-level tf32 mma.sync. B=4096,H=256,L=32,I=64.
// R15: round-robin producer specialization — warp (g+3)&15 produces chunk
// g+3 alone (32x cp.async/lane); other 15 warps run a pure consumer loop.
// mbarrier ring 4, fused 92-chunk stream, 512 thr, warp tile 32x64.

#define DEVI __device__ __forceinline__

static constexpr long long BHL = 4096LL * 256 * 32;
static constexpr long long BLc = 4096LL * 32;

static constexpr size_t HH_ONE = 32 * 65536;
static constexpr size_t II_ONE = 32 * 16384;
static constexpr size_t HH_TOT = 5 * HH_ONE;
static constexpr size_t W_TOT  = HH_TOT + 3 * II_ONE;

__device__ float g_wr[W_TOT];        // fragment-ordered tf32 weights (~48MB)
__device__ float g_scr[33554432];    // per-warp r/n scratch

// smem: A[0,131072) xm[131072,163840) ring 4x16384[163840,229376)
//       mbars[229376,229440) wptr[229440,230176) aux[230176,230912)
//       mu[230912,231424)
static constexpr unsigned OFF_MB   = 229376;
static constexpr unsigned OFF_WPTR = 229440;
static constexpr unsigned OFF_AUX  = 230176;
static constexpr unsigned OFF_MU   = 230912;
static constexpr unsigned SMEM_BYTES = 231424;

DEVI unsigned s2u(const void* p) {
    unsigned a;
    asm("{ .reg .u64 t; cvta.to.shared.u64 t, %1; cvt.u32.u64 %0, t; }"
        : "=r"(a) : "l"(p));
    return a;
}
DEVI float sigm(float v) { return __fdividef(1.f, 1.f + __expf(-v)); }
DEVI float ftanh(float x) {
    float t = __expf(-2.f * fabsf(x));
    return copysignf(__fdividef(1.f - t, 1.f + t), x);
}
DEVI float tf32r(float v) {
    uint32_t o;
    asm("cvt.rna.tf32.f32 %0, %1;" : "=r"(o) : "f"(v));
    return __uint_as_float(o);
}
DEVI unsigned aswz(int row, int k4) {
    return (unsigned)(((k4 & ~7) | ((k4 ^ row) & 7)) * 16);
}

#define MB_INIT(a, n) \
    asm volatile("mbarrier.init.shared.b64 [%0], %1;" :: "r"(a), "r"(n) : "memory")
#define MB_ARRIVE(a) \
    asm volatile("mbarrier.arrive.release.cta.shared::cta.b64 _, [%0];" \
                 :: "r"(a) : "memory")
#define MB_WAIT(a, p) do {                                                    \
    unsigned _d;                                                              \
    asm volatile("{\n\t.reg .pred P;\n\t"                                     \
        "mbarrier.try_wait.parity.acquire.cta.shared::cta.b64 P, [%1], %2;\n\t" \
        "selp.b32 %0,1,0,P;\n\t}" : "=r"(_d) : "r"(a), "r"(p) : "memory");    \
    if (!_d) {                                                                \
        asm volatile("{\n\t.reg .pred P;\n\tLW%=:\n\t"                        \
            "mbarrier.try_wait.parity.acquire.cta.shared::cta.b64 P, [%0], %1, 0x989680;\n\t" \
            "@P bra LD%=;\n\tbra LW%=;\n\tLD%=:\n\t}"                         \
            :: "r"(a), "r"(p) : "memory");                                    \
    } } while (0)
#define CPA_MB_ARRIVE(a) \
    asm volatile("cp.async.mbarrier.arrive.noinc.shared.b64 [%0];" \
                 :: "r"(a) : "memory")

// ---------- prep: fragment-ordered tf32 weight images (k16 granules) ----------
__global__ void __launch_bounds__(256)
wprep(const float* __restrict__ Whr, const float* __restrict__ Whn,
      const float* __restrict__ Whz, const float* __restrict__ W1,
      const float* __restrict__ W2,  const float* __restrict__ Wir,
      const float* __restrict__ Win, const float* __restrict__ Wiz) {
    const int bid = blockIdx.x, tid = threadIdx.x;
    const float* src;
    float* dst;
    int c;
    if (bid < 2560) {
        int w = bid >> 9, rem = bid & 511, l = rem >> 4;
        c = rem & 15;
        const float* hs[5] = {Whr, Whn, Whz, W1, W2};
        src = hs[w] + (size_t)l * 65536;
        dst = g_wr + (size_t)(w * 32 + l) * 65536 + (size_t)c * 4096;
    } else {
        int e = bid - 2560;
        int w = e >> 7, rem = e & 127, l = rem >> 2;
        c = rem & 3;
        const float* is[3] = {Wir, Win, Wiz};
        src = is[w] + (size_t)l * 16384;
        dst = g_wr + HH_TOT + (size_t)(w * 32 + l) * 16384 + (size_t)c * 4096;
    }
    const int s = tid >> 7, wc = (tid >> 5) & 3, lane = tid & 31;
#pragma unroll
    for (int j4 = 0; j4 < 4; ++j4) {
        float4 v;
        int k0 = c * 16 + s * 8 + (lane & 3);
        int n0 = wc * 64 + (2 * j4) * 8 + (lane >> 2);
        int n1 = n0 + 8;
        v.x = tf32r(src[(size_t)k0 * 256 + n0]);
        v.y = tf32r(src[(size_t)(k0 + 4) * 256 + n0]);
        v.z = tf32r(src[(size_t)k0 * 256 + n1]);
        v.w = tf32r(src[(size_t)(k0 + 4) * 256 + n1]);
        reinterpret_cast<float4*>(dst)[(s * 4 + j4) * 128 + wc * 32 + lane] = v;
    }
}

// fused stream chunk map: [0,16)Whr [16,20)Wir [20,36)Whn [36,40)Win
//                         [40,56)Whz [56,60)Wiz [60,76)W1 [76,92)W2
DEVI const float* wsrc(int g, int l) {
    const float* WH = g_wr;
    const float* WI = g_wr + HH_TOT;
    if (g < 16) return WH + (size_t)(0 * 32 + l) * 65536 + (size_t)g * 4096;
    if (g < 20) return WI + (size_t)(0 * 32 + l) * 16384 + (size_t)(g - 16) * 4096;
    if (g < 36) return WH + (size_t)(1 * 32 + l) * 65536 + (size_t)(g - 20) * 4096;
    if (g < 40) return WI + (size_t)(1 * 32 + l) * 16384 + (size_t)(g - 36) * 4096;
    if (g < 56) return WH + (size_t)(2 * 32 + l) * 65536 + (size_t)(g - 40) * 4096;
    if (g < 60) return WI + (size_t)(2 * 32 + l) * 16384 + (size_t)(g - 56) * 4096;
    if (g < 76) return WH + (size_t)(3 * 32 + l) * 65536 + (size_t)(g - 60) * 4096;
    return      WH + (size_t)(4 * 32 + l) * 65536 + (size_t)(g - 76) * 4096;
}
DEVI void achunk(int g, unsigned& rs, int& kc) {
    if (g < 16)      { rs = 1024; kc = g; }
    else if (g < 20) { rs = 256;  kc = g - 16; }
    else if (g < 36) { rs = 1024; kc = g - 20; }
    else if (g < 40) { rs = 256;  kc = g - 36; }
    else if (g < 56) { rs = 1024; kc = g - 40; }
    else if (g < 60) { rs = 256;  kc = g - 56; }
    else if (g < 76) { rs = 1024; kc = g - 60; }
    else             { rs = 1024; kc = g - 76; }
}

#define C0J (wc * 64 + j * 8 + 2 * (lane & 3))
#define R0I (wr * 32 + i * 16 + (lane >> 2))

// one warp fills a whole 16KB chunk: 32 x 16B per lane
DEVI void warp_fill(unsigned wpU, unsigned bU, unsigned mbU, int g, int lane) {
    uint64_t wp;
    asm volatile("ld.shared.u64 %0, [%1];" : "=l"(wp) : "r"(wpU + (unsigned)g * 8u));
    const char* s = (const char*)wp + (unsigned)lane * 16u;
    unsigned d = bU + (unsigned)(g & 3) * 16384u + (unsigned)lane * 16u;
#pragma unroll
    for (int q = 0; q < 32; ++q)
        asm volatile("cp.async.cg.shared.global [%0], [%1], 16;"
                     :: "r"(d + (unsigned)q * 512u), "l"(s + (size_t)q * 512));
    CPA_MB_ARRIVE(mbU + (unsigned)(g & 3) * 8u);
}

__global__ void __launch_bounds__(512, 1)
prnn_mma(const float* __restrict__ hidden, const float* __restrict__ x,
         const float* __restrict__ mask,
         const float* __restrict__ bir, const float* __restrict__ biz,
         const float* __restrict__ bin_, const float* __restrict__ bhn,
         const float* __restrict__ b1,  const float* __restrict__ b2,
         const float* __restrict__ Wmu, const float* __restrict__ bmu,
         const float* __restrict__ log_var, float* __restrict__ out) {
    extern __shared__ __align__(16) char smem[];
    const unsigned sU = s2u(smem);
    const unsigned aU = sU, xU = sU + 131072u, bU = sU + 163840u;
    const unsigned mbU = sU + OFF_MB, wpU = sU + OFF_WPTR, axU = sU + OFF_AUX;
    float* mu_s = (float*)(smem + OFF_MU);
    const int tid = threadIdx.x, lane = tid & 31, w = tid >> 5;
    const int wr = w >> 2, wc = w & 3;           // warp grid 4 x 4
    const int l = blockIdx.x & 31, b0 = (blockIdx.x >> 5) * 128;

    if (tid < 128) mu_s[tid] = 0.f;
    if (tid < 8) MB_INIT(mbU + tid * 8u, tid < 4 ? 32u : 16u);  // full:0-3 empty:4-7
    if (tid < 92) {                                  // pointer + aux tables
        uint64_t wp = (uint64_t)wsrc(tid, l);
        unsigned rs;
        int kc;
        achunk(tid, rs, kc);
        asm volatile("st.shared.u64 [%0], %1;" :: "r"(wpU + tid * 8u), "l"(wp));
        asm volatile("st.shared.v2.u32 [%0], {%1, %2};"
                     :: "r"(axU + tid * 8u), "r"(rs), "r"((unsigned)(kc * 4)));
    }

    {   // A <- tf32(h): thread = (col, row-half), scattered gmem
        const int colA = tid & 255, rh = tid >> 8;
        const float* hp = hidden + (size_t)(b0 + rh * 64) * 8192
                        + (size_t)colA * 32 + l;
#pragma unroll 4
        for (int r = 0; r < 64; ++r) {
            float v = tf32r(hp[(size_t)r * 8192]);
            int row = rh * 64 + r;
            unsigned ad = aU + (unsigned)row * 1024u + aswz(row, colA >> 2)
                        + (colA & 3) * 4u;
            asm volatile("st.shared.f32 [%0], %1;" :: "r"(ad), "f"(v));
        }
    }
    {   // xm <- tf32(x * mask)
#pragma unroll
        for (int q = 0; q < 16; ++q) {
            int idx = tid + q * 512, r = idx >> 6, k = idx & 63;
            float v = tf32r(__ldg(x + (size_t)(b0 + r) * 64 + k)
                            * __ldg(mask + k * 32 + l));
            unsigned ad = xU + (unsigned)r * 256u + aswz(r, k >> 2) + (k & 3) * 4u;
            asm volatile("st.shared.f32 [%0], %1;" :: "r"(ad), "f"(v));
        }
    }
    __syncthreads();   // A, xm, tables, mbarriers all ready

    // prologue: warps 0..2 fill chunks 0..2 (no empty-wait on first use)
    if (w < 3) warp_fill(wpU, bU, mbU, w, lane);

    float acc[2][8][4];
#pragma unroll
    for (int i = 0; i < 2; ++i)
#pragma unroll
        for (int j = 0; j < 8; ++j)
#pragma unroll
            for (int q = 0; q < 4; ++q) acc[i][j][q] = 0.f;

    float* scr = g_scr + (size_t)blockIdx.x * 32768 + (size_t)w * 2048;
#define SCRP(i, j) (scr + ((size_t)((i) * 8 + (j)) * 32 + lane) * 4)

    const int lm = lane >> 3, lr = lane & 7;
    const unsigned bfb = (unsigned)(wc * 32 + lane) * 16u;

#pragma unroll 1
    for (int g = 0; g < 92; ++g) {
        // ---- round-robin producer: warp (g+3)&15 fills chunk g+3 ----
        if (g + 3 < 92 && w == ((g + 3) & 15)) {
            int gg = g + 3;
            MB_WAIT(mbU + 32u + (unsigned)(gg & 3) * 8u,
                    (unsigned)(((gg >> 2) & 1) ^ 1));
            warp_fill(wpU, bU, mbU, gg, lane);
        }
        // ---- consumer: wait data, compute ----
        const int sl = g & 3;
        MB_WAIT(mbU + (unsigned)sl * 8u, (unsigned)((g >> 2) & 1));

        unsigned rs, k4b;
        asm volatile("ld.shared.v2.u32 {%0, %1}, [%2];"
                     : "=r"(rs), "=r"(k4b) : "r"(axU + g * 8u));
        const unsigned abase = (rs == 256u) ? xU : aU;
        const unsigned bb = bU + (unsigned)sl * 16384u;
#pragma unroll
        for (int s = 0; s < 2; ++s) {
            uint32_t bf[8][2];
#pragma unroll
            for (int j4 = 0; j4 < 4; ++j4) {
                uint32_t v0, v1, v2, v3;
                asm volatile("ld.shared.v4.b32 {%0,%1,%2,%3}, [%4];"
                    : "=r"(v0), "=r"(v1), "=r"(v2), "=r"(v3)
                    : "r"(bb + (unsigned)(s * 4 + j4) * 2048u + bfb));
                bf[2 * j4][0] = v0; bf[2 * j4][1] = v1;
                bf[2 * j4 + 1][0] = v2; bf[2 * j4 + 1][1] = v3;
            }
            uint32_t af[2][4];
#pragma unroll
            for (int i = 0; i < 2; ++i) {
                int row = wr * 32 + i * 16 + (lm & 1) * 8 + lr;
                int k4  = (int)k4b + s * 2 + (lm >> 1);
                unsigned ad = abase + (unsigned)row * rs + aswz(row, k4);
                asm volatile("ldmatrix.sync.aligned.m8n8.x4.shared.b16 "
                             "{%0,%1,%2,%3}, [%4];"
                    : "=r"(af[i][0]), "=r"(af[i][1]),
                      "=r"(af[i][2]), "=r"(af[i][3])
                    : "r"(ad));
            }
#pragma unroll
            for (int i = 0; i < 2; ++i)
#pragma unroll
                for (int j = 0; j < 8; ++j)
                    asm volatile(
                        "mma.sync.aligned.m16n8k8.row.col.f32.tf32.tf32.f32 "
                        "{%0,%1,%2,%3}, {%4,%5,%6,%7}, {%8,%9}, {%0,%1,%2,%3};"
                        : "+f"(acc[i][j][0]), "+f"(acc[i][j][1]),
                          "+f"(acc[i][j][2]), "+f"(acc[i][j][3])
                        : "r"(af[i][0]), "r"(af[i][1]),
                          "r"(af[i][2]), "r"(af[i][3]),
                          "r"(bf[j][0]), "r"(bf[j][1]));
        }
        if (lane == 0) MB_ARRIVE(mbU + 32u + (unsigned)sl * 8u);

        // ---- inlined epilogues ----
        if (g == 19) {          // r = sigmoid(acc + bir) -> scratch; acc = 0
            const float* bb2 = bir + l * 256;
#pragma unroll
            for (int i = 0; i < 2; ++i)
#pragma unroll
                for (int j = 0; j < 8; ++j) {
                    int c0 = C0J;
                    float4 v;
                    v.x = sigm(acc[i][j][0] + __ldg(bb2 + c0));
                    v.y = sigm(acc[i][j][1] + __ldg(bb2 + c0 + 1));
                    v.z = sigm(acc[i][j][2] + __ldg(bb2 + c0));
                    v.w = sigm(acc[i][j][3] + __ldg(bb2 + c0 + 1));
                    *reinterpret_cast<float4*>(SCRP(i, j)) = v;
                    acc[i][j][0] = acc[i][j][1] = acc[i][j][2] = acc[i][j][3] = 0.f;
                }
        } else if (g == 35) {   // acc = r * (acc + bhn)
            const float* bb2 = bhn + l * 256;
#pragma unroll
            for (int i = 0; i < 2; ++i)
#pragma unroll
                for (int j = 0; j < 8; ++j) {
                    int c0 = C0J;
                    float4 rv = *reinterpret_cast<const float4*>(SCRP(i, j));
                    acc[i][j][0] = rv.x * (acc[i][j][0] + __ldg(bb2 + c0));
                    acc[i][j][1] = rv.y * (acc[i][j][1] + __ldg(bb2 + c0 + 1));
                    acc[i][j][2] = rv.z * (acc[i][j][2] + __ldg(bb2 + c0));
                    acc[i][j][3] = rv.w * (acc[i][j][3] + __ldg(bb2 + c0 + 1));
                }
        } else if (g == 39) {   // n = tanh(acc + bin) -> scratch; acc = 0
            const float* bb2 = bin_ + l * 256;
#pragma unroll
            for (int i = 0; i < 2; ++i)
#pragma unroll
                for (int j = 0; j < 8; ++j) {
                    int c0 = C0J;
                    float4 v;
                    v.x = ftanh(acc[i][j][0] + __ldg(bb2 + c0));
                    v.y = ftanh(acc[i][j][1] + __ldg(bb2 + c0 + 1));
                    v.z = ftanh(acc[i][j][2] + __ldg(bb2 + c0));
                    v.w = ftanh(acc[i][j][3] + __ldg(bb2 + c0 + 1));
                    *reinterpret_cast<float4*>(SCRP(i, j)) = v;
                    acc[i][j][0] = acc[i][j][1] = acc[i][j][2] = acc[i][j][3] = 0.f;
                }
        } else if (g == 59) {   // z = sigm(acc+biz); hnew = n + z*(h-n) -> A
            __syncthreads();    // all warps done READING h through chunk 59
            const float* bb2 = biz + l * 256;
#pragma unroll
            for (int i = 0; i < 2; ++i)
#pragma unroll
                for (int j = 0; j < 8; ++j) {
                    int c0 = C0J, r0 = R0I, r1 = r0 + 8;
                    float4 nv = *reinterpret_cast<const float4*>(SCRP(i, j));
                    float zz[4];
                    zz[0] = sigm(acc[i][j][0] + __ldg(bb2 + c0));
                    zz[1] = sigm(acc[i][j][1] + __ldg(bb2 + c0 + 1));
                    zz[2] = sigm(acc[i][j][2] + __ldg(bb2 + c0));
                    zz[3] = sigm(acc[i][j][3] + __ldg(bb2 + c0 + 1));
                    const int rr[4] = {r0, r0, r1, r1};
                    const int cc[4] = {c0, c0 + 1, c0, c0 + 1};
                    const float nn[4] = {nv.x, nv.y, nv.z, nv.w};
#pragma unroll
                    for (int q = 0; q < 4; ++q) {
                        unsigned ad = aU + (unsigned)rr[q] * 1024u
                                    + aswz(rr[q], cc[q] >> 2) + (cc[q] & 3) * 4u;
                        float h;
                        asm volatile("ld.shared.f32 %0, [%1];" : "=f"(h) : "r"(ad));
                        float hv = tf32r(nn[q] + zz[q] * (h - nn[q]));
                        asm volatile("st.shared.f32 [%0], %1;" :: "r"(ad), "f"(hv));
                        acc[i][j][q] = 0.f;
                    }
                }
            __syncthreads();    // hnew visible before anyone reads at g=60
        } else if (g == 75) {   // h1 = relu(acc + b1) -> A
            __syncthreads();
            const float* bb2 = b1 + l * 256;
#pragma unroll
            for (int i = 0; i < 2; ++i)
#pragma unroll
                for (int j = 0; j < 8; ++j) {
                    int c0 = C0J, r0 = R0I, r1 = r0 + 8;
                    const int rr[4] = {r0, r0, r1, r1};
                    const int cc[4] = {c0, c0 + 1, c0, c0 + 1};
#pragma unroll
                    for (int q = 0; q < 4; ++q) {
                        float hv = tf32r(fmaxf(acc[i][j][q] + __ldg(bb2 + cc[q]), 0.f));
                        unsigned ad = aU + (unsigned)rr[q] * 1024u
                                    + aswz(rr[q], cc[q] >> 2) + (cc[q] & 3) * 4u;
                        asm volatile("st.shared.f32 [%0], %1;" :: "r"(ad), "f"(hv));
                        acc[i][j][q] = 0.f;
                    }
                }
            __syncthreads();
        }
    }

    // ---- tail: h2 = relu(acc + b2) -> out + mu ----
    {
        const float* bb2 = b2 + l * 256;
        const float* wml = Wmu + l * 256;
        float mup[2][2];
#pragma unroll
        for (int i = 0; i < 2; ++i) { mup[i][0] = 0.f; mup[i][1] = 0.f; }
#pragma unroll
        for (int i = 0; i < 2; ++i)
#pragma unroll
            for (int j = 0; j < 8; ++j) {
                int c0 = C0J, r0 = R0I, r1 = r0 + 8;
                float h2a = fmaxf(acc[i][j][0] + __ldg(bb2 + c0), 0.f);
                float h2b = fmaxf(acc[i][j][1] + __ldg(bb2 + c0 + 1), 0.f);
                float h2c = fmaxf(acc[i][j][2] + __ldg(bb2 + c0), 0.f);
                float h2d = fmaxf(acc[i][j][3] + __ldg(bb2 + c0 + 1), 0.f);
                size_t ob  = (size_t)(b0 + r0) * 8192 + l;
                size_t ob1 = (size_t)(b0 + r1) * 8192 + l;
                out[ob + (size_t)c0 * 32]        = h2a;
                out[ob + (size_t)(c0 + 1) * 32]  = h2b;
                out[ob1 + (size_t)c0 * 32]       = h2c;
                out[ob1 + (size_t)(c0 + 1) * 32] = h2d;
                mup[i][0] += h2a * __ldg(wml + c0) + h2b * __ldg(wml + c0 + 1);
                mup[i][1] += h2c * __ldg(wml + c0) + h2d * __ldg(wml + c0 + 1);
            }
#pragma unroll
        for (int i = 0; i < 2; ++i)
#pragma unroll
            for (int hq = 0; hq < 2; ++hq) {
                float v = mup[i][hq];
                v += __shfl_xor_sync(0xffffffffu, v, 1);
                v += __shfl_xor_sync(0xffffffffu, v, 2);
                if ((lane & 3) == 0)
                    atomicAdd(&mu_s[wr * 32 + i * 16 + (lane >> 2) + hq * 8], v);
            }
    }
    __syncthreads();
    if (tid < 128) {
        out[BHL + (size_t)(b0 + tid) * 32 + l] = mu_s[tid] + __ldg(bmu + l);
        out[BHL + BLc + (size_t)(b0 + tid) * 32 + l] =
            fmaxf(__ldg(log_var + l), -3.0f);
    }
}

extern "C" void kernel_launch(void* const* d_in, const int* in_sizes, int n_in,
                              void* d_out, int out_size) {
    const float* hidden  = (const float*)d_in[0];
    const float* x       = (const float*)d_in[1];
    const float* mask    = (const float*)d_in[2];
    const float* Wir     = (const float*)d_in[3];
    const float* bir     = (const float*)d_in[4];
    const float* Wiz     = (const float*)d_in[5];
    const float* biz     = (const float*)d_in[6];
    const float* Win     = (const float*)d_in[7];
    const float* bin_    = (const float*)d_in[8];
    const float* Whr     = (const float*)d_in[9];
    const float* Whz     = (const float*)d_in[10];
    const float* Whn     = (const float*)d_in[11];
    const float* bhn     = (const float*)d_in[12];
    const float* W1      = (const float*)d_in[13];
    const float* b1      = (const float*)d_in[14];
    const float* W2      = (const float*)d_in[15];
    const float* b2      = (const float*)d_in[16];
    const float* Wmu     = (const float*)d_in[17];
    const float* bmu     = (const float*)d_in[18];
    const float* log_var = (const float*)d_in[19];
    float* out = (float*)d_out;

    cudaFuncSetAttribute(prnn_mma, cudaFuncAttributeMaxDynamicSharedMemorySize,
                         SMEM_BYTES);
    wprep<<<2944, 256>>>(Whr, Whn, Whz, W1, W2, Wir, Win, Wiz);
    prnn_mma<<<1024, 512, SMEM_BYTES>>>(hidden, x, mask, bir, biz, bin_, bhn,
                                        b1, b2, Wmu, bmu, log_var, out);
}

// round 16
// speedup vs baseline: 1.5402x; 1.2091x over previous
#include <cuda_runtime.h>
#include <math.h>
#include <stdint.h>

// ParallelRNN via warp-level tf32 mma.sync. B=4096,H=256,L=32,I=64.
// R16: R15 + coalescing transpose of hidden ([B,H,L] -> [L,B,H], tf32-
// rounded) so the main kernel's A-load is 1024 wavefronts instead of 33K.

#define DEVI __device__ __forceinline__

static constexpr long long BHL = 4096LL * 256 * 32;
static constexpr long long BLc = 4096LL * 32;

static constexpr size_t HH_ONE = 32 * 65536;
static constexpr size_t II_ONE = 32 * 16384;
static constexpr size_t HH_TOT = 5 * HH_ONE;
static constexpr size_t W_TOT  = HH_TOT + 3 * II_ONE;

__device__ float g_wr[W_TOT];        // fragment-ordered tf32 weights (~48MB)
__device__ float g_scr[33554432];    // per-warp r/n scratch
__device__ float g_hT[33554432];     // hidden transposed [L][B][H], tf32 (128MB)

// smem: A[0,131072) xm[131072,163840) ring 4x16384[163840,229376)
//       mbars[229376,229440) wptr[229440,230176) aux[230176,230912)
//       mu[230912,231424)
static constexpr unsigned OFF_MB   = 229376;
static constexpr unsigned OFF_WPTR = 229440;
static constexpr unsigned OFF_AUX  = 230176;
static constexpr unsigned OFF_MU   = 230912;
static constexpr unsigned SMEM_BYTES = 231424;

DEVI unsigned s2u(const void* p) {
    unsigned a;
    asm("{ .reg .u64 t; cvta.to.shared.u64 t, %1; cvt.u32.u64 %0, t; }"
        : "=r"(a) : "l"(p));
    return a;
}
DEVI float sigm(float v) { return __fdividef(1.f, 1.f + __expf(-v)); }
DEVI float ftanh(float x) {
    float t = __expf(-2.f * fabsf(x));
    return copysignf(__fdividef(1.f - t, 1.f + t), x);
}
DEVI float tf32r(float v) {
    uint32_t o;
    asm("cvt.rna.tf32.f32 %0, %1;" : "=r"(o) : "f"(v));
    return __uint_as_float(o);
}
DEVI unsigned aswz(int row, int k4) {
    return (unsigned)(((k4 & ~7) | ((k4 ^ row) & 7)) * 16);
}

#define MB_INIT(a, n) \
    asm volatile("mbarrier.init.shared.b64 [%0], %1;" :: "r"(a), "r"(n) : "memory")
#define MB_ARRIVE(a) \
    asm volatile("mbarrier.arrive.release.cta.shared::cta.b64 _, [%0];" \
                 :: "r"(a) : "memory")
#define MB_WAIT(a, p) do {                                                    \
    unsigned _d;                                                              \
    asm volatile("{\n\t.reg .pred P;\n\t"                                     \
        "mbarrier.try_wait.parity.acquire.cta.shared::cta.b64 P, [%1], %2;\n\t" \
        "selp.b32 %0,1,0,P;\n\t}" : "=r"(_d) : "r"(a), "r"(p) : "memory");    \
    if (!_d) {                                                                \
        asm volatile("{\n\t.reg .pred P;\n\tLW%=:\n\t"                        \
            "mbarrier.try_wait.parity.acquire.cta.shared::cta.b64 P, [%0], %1, 0x989680;\n\t" \
            "@P bra LD%=;\n\tbra LW%=;\n\tLD%=:\n\t}"                         \
            :: "r"(a), "r"(p) : "memory");                                    \
    } } while (0)
#define CPA_MB_ARRIVE(a) \
    asm volatile("cp.async.mbarrier.arrive.noinc.shared.b64 [%0];" \
                 :: "r"(a) : "memory")

// ---------- prep 1: fragment-ordered tf32 weight images ----------
__global__ void __launch_bounds__(256)
wprep(const float* __restrict__ Whr, const float* __restrict__ Whn,
      const float* __restrict__ Whz, const float* __restrict__ W1,
      const float* __restrict__ W2,  const float* __restrict__ Wir,
      const float* __restrict__ Win, const float* __restrict__ Wiz) {
    const int bid = blockIdx.x, tid = threadIdx.x;
    const float* src;
    float* dst;
    int c;
    if (bid < 2560) {
        int w = bid >> 9, rem = bid & 511, l = rem >> 4;
        c = rem & 15;
        const float* hs[5] = {Whr, Whn, Whz, W1, W2};
        src = hs[w] + (size_t)l * 65536;
        dst = g_wr + (size_t)(w * 32 + l) * 65536 + (size_t)c * 4096;
    } else {
        int e = bid - 2560;
        int w = e >> 7, rem = e & 127, l = rem >> 2;
        c = rem & 3;
        const float* is[3] = {Wir, Win, Wiz};
        src = is[w] + (size_t)l * 16384;
        dst = g_wr + HH_TOT + (size_t)(w * 32 + l) * 16384 + (size_t)c * 4096;
    }
    const int s = tid >> 7, wc = (tid >> 5) & 3, lane = tid & 31;
#pragma unroll
    for (int j4 = 0; j4 < 4; ++j4) {
        float4 v;
        int k0 = c * 16 + s * 8 + (lane & 3);
        int n0 = wc * 64 + (2 * j4) * 8 + (lane >> 2);
        int n1 = n0 + 8;
        v.x = tf32r(src[(size_t)k0 * 256 + n0]);
        v.y = tf32r(src[(size_t)(k0 + 4) * 256 + n0]);
        v.z = tf32r(src[(size_t)k0 * 256 + n1]);
        v.w = tf32r(src[(size_t)(k0 + 4) * 256 + n1]);
        reinterpret_cast<float4*>(dst)[(s * 4 + j4) * 128 + wc * 32 + lane] = v;
    }
}

// ---------- prep 2: hidden [B,H,L] -> g_hT [L,B,H] (tf32-rounded) ----------
__global__ void __launch_bounds__(256)
htrans(const float* __restrict__ hidden) {
    __shared__ float stg[32 * 257];
    const int b = blockIdx.x, tid = threadIdx.x;
    const float* src = hidden + (size_t)b * 8192;
#pragma unroll
    for (int q = 0; q < 32; ++q) {          // coalesced read: 8192 floats
        int idx = tid + q * 256;
        int h = idx >> 5, l = idx & 31;
        stg[l * 257 + h] = tf32r(src[idx]);
    }
    __syncthreads();
#pragma unroll
    for (int q = 0; q < 32; ++q) {          // coalesced write per l-row
        int idx = tid + q * 256;
        int l = idx >> 8, h = idx & 255;
        g_hT[(size_t)l * 1048576 + (size_t)b * 256 + h] = stg[l * 257 + h];
    }
}

// fused stream chunk map: [0,16)Whr [16,20)Wir [20,36)Whn [36,40)Win
//                         [40,56)Whz [56,60)Wiz [60,76)W1 [76,92)W2
DEVI const float* wsrc(int g, int l) {
    const float* WH = g_wr;
    const float* WI = g_wr + HH_TOT;
    if (g < 16) return WH + (size_t)(0 * 32 + l) * 65536 + (size_t)g * 4096;
    if (g < 20) return WI + (size_t)(0 * 32 + l) * 16384 + (size_t)(g - 16) * 4096;
    if (g < 36) return WH + (size_t)(1 * 32 + l) * 65536 + (size_t)(g - 20) * 4096;
    if (g < 40) return WI + (size_t)(1 * 32 + l) * 16384 + (size_t)(g - 36) * 4096;
    if (g < 56) return WH + (size_t)(2 * 32 + l) * 65536 + (size_t)(g - 40) * 4096;
    if (g < 60) return WI + (size_t)(2 * 32 + l) * 16384 + (size_t)(g - 56) * 4096;
    if (g < 76) return WH + (size_t)(3 * 32 + l) * 65536 + (size_t)(g - 60) * 4096;
    return      WH + (size_t)(4 * 32 + l) * 65536 + (size_t)(g - 76) * 4096;
}
DEVI void achunk(int g, unsigned& rs, int& kc) {
    if (g < 16)      { rs = 1024; kc = g; }
    else if (g < 20) { rs = 256;  kc = g - 16; }
    else if (g < 36) { rs = 1024; kc = g - 20; }
    else if (g < 40) { rs = 256;  kc = g - 36; }
    else if (g < 56) { rs = 1024; kc = g - 40; }
    else if (g < 60) { rs = 256;  kc = g - 56; }
    else if (g < 76) { rs = 1024; kc = g - 60; }
    else             { rs = 1024; kc = g - 76; }
}

#define C0J (wc * 64 + j * 8 + 2 * (lane & 3))
#define R0I (wr * 32 + i * 16 + (lane >> 2))

// one warp fills a whole 16KB chunk: 32 x 16B per lane
DEVI void warp_fill(unsigned wpU, unsigned bU, unsigned mbU, int g, int lane) {
    uint64_t wp;
    asm volatile("ld.shared.u64 %0, [%1];" : "=l"(wp) : "r"(wpU + (unsigned)g * 8u));
    const char* s = (const char*)wp + (unsigned)lane * 16u;
    unsigned d = bU + (unsigned)(g & 3) * 16384u + (unsigned)lane * 16u;
#pragma unroll
    for (int q = 0; q < 32; ++q)
        asm volatile("cp.async.cg.shared.global [%0], [%1], 16;"
                     :: "r"(d + (unsigned)q * 512u), "l"(s + (size_t)q * 512));
    CPA_MB_ARRIVE(mbU + (unsigned)(g & 3) * 8u);
}

__global__ void __launch_bounds__(512, 1)
prnn_mma(const float* __restrict__ x, const float* __restrict__ mask,
         const float* __restrict__ bir, const float* __restrict__ biz,
         const float* __restrict__ bin_, const float* __restrict__ bhn,
         const float* __restrict__ b1,  const float* __restrict__ b2,
         const float* __restrict__ Wmu, const float* __restrict__ bmu,
         const float* __restrict__ log_var, float* __restrict__ out) {
    extern __shared__ __align__(16) char smem[];
    const unsigned sU = s2u(smem);
    const unsigned aU = sU, xU = sU + 131072u, bU = sU + 163840u;
    const unsigned mbU = sU + OFF_MB, wpU = sU + OFF_WPTR, axU = sU + OFF_AUX;
    float* mu_s = (float*)(smem + OFF_MU);
    const int tid = threadIdx.x, lane = tid & 31, w = tid >> 5;
    const int wr = w >> 2, wc = w & 3;           // warp grid 4 x 4
    const int l = blockIdx.x & 31, b0 = (blockIdx.x >> 5) * 128;

    if (tid < 128) mu_s[tid] = 0.f;
    if (tid < 8) MB_INIT(mbU + tid * 8u, tid < 4 ? 32u : 16u);  // full:0-3 empty:4-7
    if (tid < 92) {                                  // pointer + aux tables
        uint64_t wp = (uint64_t)wsrc(tid, l);
        unsigned rs;
        int kc;
        achunk(tid, rs, kc);
        asm volatile("st.shared.u64 [%0], %1;" :: "r"(wpU + tid * 8u), "l"(wp));
        asm volatile("st.shared.v2.u32 [%0], {%1, %2};"
                     :: "r"(axU + tid * 8u), "r"(rs), "r"((unsigned)(kc * 4)));
    }

    {   // A <- g_hT[l, b0:b0+128, :] — coalesced float4, pre-rounded
        const float4* hp4 = reinterpret_cast<const float4*>(
            g_hT + (size_t)l * 1048576 + (size_t)b0 * 256);
#pragma unroll
        for (int q = 0; q < 16; ++q) {
            int f = tid + q * 512;               // f in [0, 8192)
            int row = f >> 6, c4 = f & 63;
            float4 v = hp4[f];
            unsigned ad = aU + (unsigned)row * 1024u + aswz(row, c4);
            asm volatile("st.shared.v4.b32 [%0], {%1, %2, %3, %4};"
                         :: "r"(ad), "r"(__float_as_uint(v.x)),
                            "r"(__float_as_uint(v.y)), "r"(__float_as_uint(v.z)),
                            "r"(__float_as_uint(v.w)));
        }
    }
    {   // xm <- tf32(x * mask)
#pragma unroll
        for (int q = 0; q < 16; ++q) {
            int idx = tid + q * 512, r = idx >> 6, k = idx & 63;
            float v = tf32r(__ldg(x + (size_t)(b0 + r) * 64 + k)
                            * __ldg(mask + k * 32 + l));
            unsigned ad = xU + (unsigned)r * 256u + aswz(r, k >> 2) + (k & 3) * 4u;
            asm volatile("st.shared.f32 [%0], %1;" :: "r"(ad), "f"(v));
        }
    }
    __syncthreads();   // A, xm, tables, mbarriers all ready

    // prologue: warps 0..2 fill chunks 0..2 (no empty-wait on first use)
    if (w < 3) warp_fill(wpU, bU, mbU, w, lane);

    float acc[2][8][4];
#pragma unroll
    for (int i = 0; i < 2; ++i)
#pragma unroll
        for (int j = 0; j < 8; ++j)
#pragma unroll
            for (int q = 0; q < 4; ++q) acc[i][j][q] = 0.f;

    float* scr = g_scr + (size_t)blockIdx.x * 32768 + (size_t)w * 2048;
#define SCRP(i, j) (scr + ((size_t)((i) * 8 + (j)) * 32 + lane) * 4)

    const int lm = lane >> 3, lr = lane & 7;
    const unsigned bfb = (unsigned)(wc * 32 + lane) * 16u;

#pragma unroll 1
    for (int g = 0; g < 92; ++g) {
        // ---- round-robin producer: warp (g+3)&15 fills chunk g+3 ----
        if (g + 3 < 92 && w == ((g + 3) & 15)) {
            int gg = g + 3;
            MB_WAIT(mbU + 32u + (unsigned)(gg & 3) * 8u,
                    (unsigned)(((gg >> 2) & 1) ^ 1));
            warp_fill(wpU, bU, mbU, gg, lane);
        }
        // ---- consumer: wait data, compute ----
        const int sl = g & 3;
        MB_WAIT(mbU + (unsigned)sl * 8u, (unsigned)((g >> 2) & 1));

        unsigned rs, k4b;
        asm volatile("ld.shared.v2.u32 {%0, %1}, [%2];"
                     : "=r"(rs), "=r"(k4b) : "r"(axU + g * 8u));
        const unsigned abase = (rs == 256u) ? xU : aU;
        const unsigned bb = bU + (unsigned)sl * 16384u;
#pragma unroll
        for (int s = 0; s < 2; ++s) {
            uint32_t bf[8][2];
#pragma unroll
            for (int j4 = 0; j4 < 4; ++j4) {
                uint32_t v0, v1, v2, v3;
                asm volatile("ld.shared.v4.b32 {%0,%1,%2,%3}, [%4];"
                    : "=r"(v0), "=r"(v1), "=r"(v2), "=r"(v3)
                    : "r"(bb + (unsigned)(s * 4 + j4) * 2048u + bfb));
                bf[2 * j4][0] = v0; bf[2 * j4][1] = v1;
                bf[2 * j4 + 1][0] = v2; bf[2 * j4 + 1][1] = v3;
            }
            uint32_t af[2][4];
#pragma unroll
            for (int i = 0; i < 2; ++i) {
                int row = wr * 32 + i * 16 + (lm & 1) * 8 + lr;
                int k4  = (int)k4b + s * 2 + (lm >> 1);
                unsigned ad = abase + (unsigned)row * rs + aswz(row, k4);
                asm volatile("ldmatrix.sync.aligned.m8n8.x4.shared.b16 "
                             "{%0,%1,%2,%3}, [%4];"
                    : "=r"(af[i][0]), "=r"(af[i][1]),
                      "=r"(af[i][2]), "=r"(af[i][3])
                    : "r"(ad));
            }
#pragma unroll
            for (int i = 0; i < 2; ++i)
#pragma unroll
                for (int j = 0; j < 8; ++j)
                    asm volatile(
                        "mma.sync.aligned.m16n8k8.row.col.f32.tf32.tf32.f32 "
                        "{%0,%1,%2,%3}, {%4,%5,%6,%7}, {%8,%9}, {%0,%1,%2,%3};"
                        : "+f"(acc[i][j][0]), "+f"(acc[i][j][1]),
                          "+f"(acc[i][j][2]), "+f"(acc[i][j][3])
                        : "r"(af[i][0]), "r"(af[i][1]),
                          "r"(af[i][2]), "r"(af[i][3]),
                          "r"(bf[j][0]), "r"(bf[j][1]));
        }
        if (lane == 0) MB_ARRIVE(mbU + 32u + (unsigned)sl * 8u);

        // ---- inlined epilogues ----
        if (g == 19) {          // r = sigmoid(acc + bir) -> scratch; acc = 0
            const float* bb2 = bir + l * 256;
#pragma unroll
            for (int i = 0; i < 2; ++i)
#pragma unroll
                for (int j = 0; j < 8; ++j) {
                    int c0 = C0J;
                    float4 v;
                    v.x = sigm(acc[i][j][0] + __ldg(bb2 + c0));
                    v.y = sigm(acc[i][j][1] + __ldg(bb2 + c0 + 1));
                    v.z = sigm(acc[i][j][2] + __ldg(bb2 + c0));
                    v.w = sigm(acc[i][j][3] + __ldg(bb2 + c0 + 1));
                    *reinterpret_cast<float4*>(SCRP(i, j)) = v;
                    acc[i][j][0] = acc[i][j][1] = acc[i][j][2] = acc[i][j][3] = 0.f;
                }
        } else if (g == 35) {   // acc = r * (acc + bhn)
            const float* bb2 = bhn + l * 256;
#pragma unroll
            for (int i = 0; i < 2; ++i)
#pragma unroll
                for (int j = 0; j < 8; ++j) {
                    int c0 = C0J;
                    float4 rv = *reinterpret_cast<const float4*>(SCRP(i, j));
                    acc[i][j][0] = rv.x * (acc[i][j][0] + __ldg(bb2 + c0));
                    acc[i][j][1] = rv.y * (acc[i][j][1] + __ldg(bb2 + c0 + 1));
                    acc[i][j][2] = rv.z * (acc[i][j][2] + __ldg(bb2 + c0));
                    acc[i][j][3] = rv.w * (acc[i][j][3] + __ldg(bb2 + c0 + 1));
                }
        } else if (g == 39) {   // n = tanh(acc + bin) -> scratch; acc = 0
            const float* bb2 = bin_ + l * 256;
#pragma unroll
            for (int i = 0; i < 2; ++i)
#pragma unroll
                for (int j = 0; j < 8; ++j) {
                    int c0 = C0J;
                    float4 v;
                    v.x = ftanh(acc[i][j][0] + __ldg(bb2 + c0));
                    v.y = ftanh(acc[i][j][1] + __ldg(bb2 + c0 + 1));
                    v.z = ftanh(acc[i][j][2] + __ldg(bb2 + c0));
                    v.w = ftanh(acc[i][j][3] + __ldg(bb2 + c0 + 1));
                    *reinterpret_cast<float4*>(SCRP(i, j)) = v;
                    acc[i][j][0] = acc[i][j][1] = acc[i][j][2] = acc[i][j][3] = 0.f;
                }
        } else if (g == 59) {   // z = sigm(acc+biz); hnew = n + z*(h-n) -> A
            __syncthreads();    // all warps done READING h through chunk 59
            const float* bb2 = biz + l * 256;
#pragma unroll
            for (int i = 0; i < 2; ++i)
#pragma unroll
                for (int j = 0; j < 8; ++j) {
                    int c0 = C0J, r0 = R0I, r1 = r0 + 8;
                    float4 nv = *reinterpret_cast<const float4*>(SCRP(i, j));
                    float zz[4];
                    zz[0] = sigm(acc[i][j][0] + __ldg(bb2 + c0));
                    zz[1] = sigm(acc[i][j][1] + __ldg(bb2 + c0 + 1));
                    zz[2] = sigm(acc[i][j][2] + __ldg(bb2 + c0));
                    zz[3] = sigm(acc[i][j][3] + __ldg(bb2 + c0 + 1));
                    const int rr[4] = {r0, r0, r1, r1};
                    const int cc[4] = {c0, c0 + 1, c0, c0 + 1};
                    const float nn[4] = {nv.x, nv.y, nv.z, nv.w};
#pragma unroll
                    for (int q = 0; q < 4; ++q) {
                        unsigned ad = aU + (unsigned)rr[q] * 1024u
                                    + aswz(rr[q], cc[q] >> 2) + (cc[q] & 3) * 4u;
                        float h;
                        asm volatile("ld.shared.f32 %0, [%1];" : "=f"(h) : "r"(ad));
                        float hv = tf32r(nn[q] + zz[q] * (h - nn[q]));
                        asm volatile("st.shared.f32 [%0], %1;" :: "r"(ad), "f"(hv));
                        acc[i][j][q] = 0.f;
                    }
                }
            __syncthreads();    // hnew visible before anyone reads at g=60
        } else if (g == 75) {   // h1 = relu(acc + b1) -> A
            __syncthreads();
            const float* bb2 = b1 + l * 256;
#pragma unroll
            for (int i = 0; i < 2; ++i)
#pragma unroll
                for (int j = 0; j < 8; ++j) {
                    int c0 = C0J, r0 = R0I, r1 = r0 + 8;
                    const int rr[4] = {r0, r0, r1, r1};
                    const int cc[4] = {c0, c0 + 1, c0, c0 + 1};
#pragma unroll
                    for (int q = 0; q < 4; ++q) {
                        float hv = tf32r(fmaxf(acc[i][j][q] + __ldg(bb2 + cc[q]), 0.f));
                        unsigned ad = aU + (unsigned)rr[q] * 1024u
                                    + aswz(rr[q], cc[q] >> 2) + (cc[q] & 3) * 4u;
                        asm volatile("st.shared.f32 [%0], %1;" :: "r"(ad), "f"(hv));
                        acc[i][j][q] = 0.f;
                    }
                }
            __syncthreads();
        }
    }

    // ---- tail: h2 = relu(acc + b2) -> out + mu ----
    {
        const float* bb2 = b2 + l * 256;
        const float* wml = Wmu + l * 256;
        float mup[2][2];
#pragma unroll
        for (int i = 0; i < 2; ++i) { mup[i][0] = 0.f; mup[i][1] = 0.f; }
#pragma unroll
        for (int i = 0; i < 2; ++i)
#pragma unroll
            for (int j = 0; j < 8; ++j) {
                int c0 = C0J, r0 = R0I, r1 = r0 + 8;
                float h2a = fmaxf(acc[i][j][0] + __ldg(bb2 + c0), 0.f);
                float h2b = fmaxf(acc[i][j][1] + __ldg(bb2 + c0 + 1), 0.f);
                float h2c = fmaxf(acc[i][j][2] + __ldg(bb2 + c0), 0.f);
                float h2d = fmaxf(acc[i][j][3] + __ldg(bb2 + c0 + 1), 0.f);
                size_t ob  = (size_t)(b0 + r0) * 8192 + l;
                size_t ob1 = (size_t)(b0 + r1) * 8192 + l;
                out[ob + (size_t)c0 * 32]        = h2a;
                out[ob + (size_t)(c0 + 1) * 32]  = h2b;
                out[ob1 + (size_t)c0 * 32]       = h2c;
                out[ob1 + (size_t)(c0 + 1) * 32] = h2d;
                mup[i][0] += h2a * __ldg(wml + c0) + h2b * __ldg(wml + c0 + 1);
                mup[i][1] += h2c * __ldg(wml + c0) + h2d * __ldg(wml + c0 + 1);
            }
#pragma unroll
        for (int i = 0; i < 2; ++i)
#pragma unroll
            for (int hq = 0; hq < 2; ++hq) {
                float v = mup[i][hq];
                v += __shfl_xor_sync(0xffffffffu, v, 1);
                v += __shfl_xor_sync(0xffffffffu, v, 2);
                if ((lane & 3) == 0)
                    atomicAdd(&mu_s[wr * 32 + i * 16 + (lane >> 2) + hq * 8], v);
            }
    }
    __syncthreads();
    if (tid < 128) {
        out[BHL + (size_t)(b0 + tid) * 32 + l] = mu_s[tid] + __ldg(bmu + l);
        out[BHL + BLc + (size_t)(b0 + tid) * 32 + l] =
            fmaxf(__ldg(log_var + l), -3.0f);
    }
}

extern "C" void kernel_launch(void* const* d_in, const int* in_sizes, int n_in,
                              void* d_out, int out_size) {
    const float* hidden  = (const float*)d_in[0];
    const float* x       = (const float*)d_in[1];
    const float* mask    = (const float*)d_in[2];
    const float* Wir     = (const float*)d_in[3];
    const float* bir     = (const float*)d_in[4];
    const float* Wiz     = (const float*)d_in[5];
    const float* biz     = (const float*)d_in[6];
    const float* Win     = (const float*)d_in[7];
    const float* bin_    = (const float*)d_in[8];
    const float* Whr     = (const float*)d_in[9];
    const float* Whz     = (const float*)d_in[10];
    const float* Whn     = (const float*)d_in[11];
    const float* bhn     = (const float*)d_in[12];
    const float* W1      = (const float*)d_in[13];
    const float* b1      = (const float*)d_in[14];
    const float* W2      = (const float*)d_in[15];
    const float* b2      = (const float*)d_in[16];
    const float* Wmu     = (const float*)d_in[17];
    const float* bmu     = (const float*)d_in[18];
    const float* log_var = (const float*)d_in[19];
    float* out = (float*)d_out;

    cudaFuncSetAttribute(prnn_mma, cudaFuncAttributeMaxDynamicSharedMemorySize,
                         SMEM_BYTES);
    wprep<<<2944, 256>>>(Whr, Whn, Whz, W1, W2, Wir, Win, Wiz);
    htrans<<<4096, 256>>>(hidden);
    prnn_mma<<<1024, 512, SMEM_BYTES>>>(x, mask, bir, biz, bin_, bhn,
                                        b1, b2, Wmu, bmu, log_var, out);
}

// round 17
// speedup vs baseline: 1.8556x; 1.2048x over previous
#include <cuda_runtime.h>
#include <math.h>
#include <stdint.h>

// ParallelRNN via warp-level tf32 mma.sync. B=4096,H=256,L=32,I=64.
// R17: R16 + out-store descatter (h2 -> g_oT[L,B,H] float2, coalescing
// otrans kernel writes out[B,H,L]) + fused prep (wprep|htrans one launch).

#define DEVI __device__ __forceinline__

static constexpr long long BHL = 4096LL * 256 * 32;
static constexpr long long BLc = 4096LL * 32;

static constexpr size_t HH_ONE = 32 * 65536;
static constexpr size_t II_ONE = 32 * 16384;
static constexpr size_t HH_TOT = 5 * HH_ONE;
static constexpr size_t W_TOT  = HH_TOT + 3 * II_ONE;

__device__ float g_wr[W_TOT];        // fragment-ordered tf32 weights (~48MB)
__device__ float g_scr[33554432];    // per-warp r/n scratch
__device__ float g_hT[33554432];     // hidden transposed [L][B][H], tf32
__device__ float g_oT[33554432];     // h2 transposed [L][B][H]

// smem: A[0,131072) xm[131072,163840) ring 4x16384[163840,229376)
//       mbars[229376,229440) wptr[229440,230176) aux[230176,230912)
//       mu[230912,231424)
static constexpr unsigned OFF_MB   = 229376;
static constexpr unsigned OFF_WPTR = 229440;
static constexpr unsigned OFF_AUX  = 230176;
static constexpr unsigned OFF_MU   = 230912;
static constexpr unsigned SMEM_BYTES = 231424;

DEVI unsigned s2u(const void* p) {
    unsigned a;
    asm("{ .reg .u64 t; cvta.to.shared.u64 t, %1; cvt.u32.u64 %0, t; }"
        : "=r"(a) : "l"(p));
    return a;
}
DEVI float sigm(float v) { return __fdividef(1.f, 1.f + __expf(-v)); }
DEVI float ftanh(float x) {
    float t = __expf(-2.f * fabsf(x));
    return copysignf(__fdividef(1.f - t, 1.f + t), x);
}
DEVI float tf32r(float v) {
    uint32_t o;
    asm("cvt.rna.tf32.f32 %0, %1;" : "=r"(o) : "f"(v));
    return __uint_as_float(o);
}
DEVI unsigned aswz(int row, int k4) {
    return (unsigned)(((k4 & ~7) | ((k4 ^ row) & 7)) * 16);
}

#define MB_INIT(a, n) \
    asm volatile("mbarrier.init.shared.b64 [%0], %1;" :: "r"(a), "r"(n) : "memory")
#define MB_ARRIVE(a) \
    asm volatile("mbarrier.arrive.release.cta.shared::cta.b64 _, [%0];" \
                 :: "r"(a) : "memory")
#define MB_WAIT(a, p) do {                                                    \
    unsigned _d;                                                              \
    asm volatile("{\n\t.reg .pred P;\n\t"                                     \
        "mbarrier.try_wait.parity.acquire.cta.shared::cta.b64 P, [%1], %2;\n\t" \
        "selp.b32 %0,1,0,P;\n\t}" : "=r"(_d) : "r"(a), "r"(p) : "memory");    \
    if (!_d) {                                                                \
        asm volatile("{\n\t.reg .pred P;\n\tLW%=:\n\t"                        \
            "mbarrier.try_wait.parity.acquire.cta.shared::cta.b64 P, [%0], %1, 0x989680;\n\t" \
            "@P bra LD%=;\n\tbra LW%=;\n\tLD%=:\n\t}"                         \
            :: "r"(a), "r"(p) : "memory");                                    \
    } } while (0)
#define CPA_MB_ARRIVE(a) \
    asm volatile("cp.async.mbarrier.arrive.noinc.shared.b64 [%0];" \
                 :: "r"(a) : "memory")

// ---------- fused prep: wprep (blocks 0..2943) | htrans (blocks 2944..7039) ----------
__global__ void __launch_bounds__(256)
prep(const float* __restrict__ Whr, const float* __restrict__ Whn,
     const float* __restrict__ Whz, const float* __restrict__ W1,
     const float* __restrict__ W2,  const float* __restrict__ Wir,
     const float* __restrict__ Win, const float* __restrict__ Wiz,
     const float* __restrict__ hidden) {
    __shared__ float stg[32 * 257];
    const int bid = blockIdx.x, tid = threadIdx.x;
    if (bid < 2944) {   // weight fragment images
        const float* src;
        float* dst;
        int c;
        if (bid < 2560) {
            int w = bid >> 9, rem = bid & 511, l = rem >> 4;
            c = rem & 15;
            const float* hs[5] = {Whr, Whn, Whz, W1, W2};
            src = hs[w] + (size_t)l * 65536;
            dst = g_wr + (size_t)(w * 32 + l) * 65536 + (size_t)c * 4096;
        } else {
            int e = bid - 2560;
            int w = e >> 7, rem = e & 127, l = rem >> 2;
            c = rem & 3;
            const float* is[3] = {Wir, Win, Wiz};
            src = is[w] + (size_t)l * 16384;
            dst = g_wr + HH_TOT + (size_t)(w * 32 + l) * 16384 + (size_t)c * 4096;
        }
        const int s = tid >> 7, wc = (tid >> 5) & 3, lane = tid & 31;
#pragma unroll
        for (int j4 = 0; j4 < 4; ++j4) {
            float4 v;
            int k0 = c * 16 + s * 8 + (lane & 3);
            int n0 = wc * 64 + (2 * j4) * 8 + (lane >> 2);
            int n1 = n0 + 8;
            v.x = tf32r(src[(size_t)k0 * 256 + n0]);
            v.y = tf32r(src[(size_t)(k0 + 4) * 256 + n0]);
            v.z = tf32r(src[(size_t)k0 * 256 + n1]);
            v.w = tf32r(src[(size_t)(k0 + 4) * 256 + n1]);
            reinterpret_cast<float4*>(dst)[(s * 4 + j4) * 128 + wc * 32 + lane] = v;
        }
    } else {            // hidden [B,H,L] -> g_hT [L,B,H] (tf32)
        const int b = bid - 2944;
        const float* src = hidden + (size_t)b * 8192;
#pragma unroll
        for (int q = 0; q < 32; ++q) {
            int idx = tid + q * 256;
            int h = idx >> 5, l = idx & 31;
            stg[l * 257 + h] = tf32r(src[idx]);
        }
        __syncthreads();
#pragma unroll
        for (int q = 0; q < 32; ++q) {
            int idx = tid + q * 256;
            int l = idx >> 8, h = idx & 255;
            g_hT[(size_t)l * 1048576 + (size_t)b * 256 + h] = stg[l * 257 + h];
        }
    }
}

// ---------- epilogue: g_oT [L,B,H] -> out [B,H,L] (coalesced both sides) ----------
__global__ void __launch_bounds__(256)
otrans(float* __restrict__ out) {
    __shared__ float stg[32 * 257];
    const int b = blockIdx.x, tid = threadIdx.x;
#pragma unroll
    for (int q = 0; q < 32; ++q) {          // coalesced read per l-row
        int idx = tid + q * 256;
        int l = idx >> 8, h = idx & 255;
        stg[l * 257 + h] = g_oT[(size_t)l * 1048576 + (size_t)b * 256 + h];
    }
    __syncthreads();
    float* dst = out + (size_t)b * 8192;
#pragma unroll
    for (int q = 0; q < 32; ++q) {          // coalesced write: 8192 floats
        int idx = tid + q * 256;
        int h = idx >> 5, l = idx & 31;
        dst[idx] = stg[l * 257 + h];
    }
}

// fused stream chunk map: [0,16)Whr [16,20)Wir [20,36)Whn [36,40)Win
//                         [40,56)Whz [56,60)Wiz [60,76)W1 [76,92)W2
DEVI const float* wsrc(int g, int l) {
    const float* WH = g_wr;
    const float* WI = g_wr + HH_TOT;
    if (g < 16) return WH + (size_t)(0 * 32 + l) * 65536 + (size_t)g * 4096;
    if (g < 20) return WI + (size_t)(0 * 32 + l) * 16384 + (size_t)(g - 16) * 4096;
    if (g < 36) return WH + (size_t)(1 * 32 + l) * 65536 + (size_t)(g - 20) * 4096;
    if (g < 40) return WI + (size_t)(1 * 32 + l) * 16384 + (size_t)(g - 36) * 4096;
    if (g < 56) return WH + (size_t)(2 * 32 + l) * 65536 + (size_t)(g - 40) * 4096;
    if (g < 60) return WI + (size_t)(2 * 32 + l) * 16384 + (size_t)(g - 56) * 4096;
    if (g < 76) return WH + (size_t)(3 * 32 + l) * 65536 + (size_t)(g - 60) * 4096;
    return      WH + (size_t)(4 * 32 + l) * 65536 + (size_t)(g - 76) * 4096;
}
DEVI void achunk(int g, unsigned& rs, int& kc) {
    if (g < 16)      { rs = 1024; kc = g; }
    else if (g < 20) { rs = 256;  kc = g - 16; }
    else if (g < 36) { rs = 1024; kc = g - 20; }
    else if (g < 40) { rs = 256;  kc = g - 36; }
    else if (g < 56) { rs = 1024; kc = g - 40; }
    else if (g < 60) { rs = 256;  kc = g - 56; }
    else if (g < 76) { rs = 1024; kc = g - 60; }
    else             { rs = 1024; kc = g - 76; }
}

#define C0J (wc * 64 + j * 8 + 2 * (lane & 3))
#define R0I (wr * 32 + i * 16 + (lane >> 2))

// one warp fills a whole 16KB chunk: 32 x 16B per lane
DEVI void warp_fill(unsigned wpU, unsigned bU, unsigned mbU, int g, int lane) {
    uint64_t wp;
    asm volatile("ld.shared.u64 %0, [%1];" : "=l"(wp) : "r"(wpU + (unsigned)g * 8u));
    const char* s = (const char*)wp + (unsigned)lane * 16u;
    unsigned d = bU + (unsigned)(g & 3) * 16384u + (unsigned)lane * 16u;
#pragma unroll
    for (int q = 0; q < 32; ++q)
        asm volatile("cp.async.cg.shared.global [%0], [%1], 16;"
                     :: "r"(d + (unsigned)q * 512u), "l"(s + (size_t)q * 512));
    CPA_MB_ARRIVE(mbU + (unsigned)(g & 3) * 8u);
}

__global__ void __launch_bounds__(512, 1)
prnn_mma(const float* __restrict__ x, const float* __restrict__ mask,
         const float* __restrict__ bir, const float* __restrict__ biz,
         const float* __restrict__ bin_, const float* __restrict__ bhn,
         const float* __restrict__ b1,  const float* __restrict__ b2,
         const float* __restrict__ Wmu, const float* __restrict__ bmu,
         const float* __restrict__ log_var, float* __restrict__ out) {
    extern __shared__ __align__(16) char smem[];
    const unsigned sU = s2u(smem);
    const unsigned aU = sU, xU = sU + 131072u, bU = sU + 163840u;
    const unsigned mbU = sU + OFF_MB, wpU = sU + OFF_WPTR, axU = sU + OFF_AUX;
    float* mu_s = (float*)(smem + OFF_MU);
    const int tid = threadIdx.x, lane = tid & 31, w = tid >> 5;
    const int wr = w >> 2, wc = w & 3;           // warp grid 4 x 4
    const int l = blockIdx.x & 31, b0 = (blockIdx.x >> 5) * 128;

    if (tid < 128) mu_s[tid] = 0.f;
    if (tid < 8) MB_INIT(mbU + tid * 8u, tid < 4 ? 32u : 16u);  // full:0-3 empty:4-7
    if (tid < 92) {                                  // pointer + aux tables
        uint64_t wp = (uint64_t)wsrc(tid, l);
        unsigned rs;
        int kc;
        achunk(tid, rs, kc);
        asm volatile("st.shared.u64 [%0], %1;" :: "r"(wpU + tid * 8u), "l"(wp));
        asm volatile("st.shared.v2.u32 [%0], {%1, %2};"
                     :: "r"(axU + tid * 8u), "r"(rs), "r"((unsigned)(kc * 4)));
    }

    {   // A <- g_hT[l, b0:b0+128, :] — coalesced float4, pre-rounded
        const float4* hp4 = reinterpret_cast<const float4*>(
            g_hT + (size_t)l * 1048576 + (size_t)b0 * 256);
#pragma unroll
        for (int q = 0; q < 16; ++q) {
            int f = tid + q * 512;               // f in [0, 8192)
            int row = f >> 6, c4 = f & 63;
            float4 v = hp4[f];
            unsigned ad = aU + (unsigned)row * 1024u + aswz(row, c4);
            asm volatile("st.shared.v4.b32 [%0], {%1, %2, %3, %4};"
                         :: "r"(ad), "r"(__float_as_uint(v.x)),
                            "r"(__float_as_uint(v.y)), "r"(__float_as_uint(v.z)),
                            "r"(__float_as_uint(v.w)));
        }
    }
    {   // xm <- tf32(x * mask)
#pragma unroll
        for (int q = 0; q < 16; ++q) {
            int idx = tid + q * 512, r = idx >> 6, k = idx & 63;
            float v = tf32r(__ldg(x + (size_t)(b0 + r) * 64 + k)
                            * __ldg(mask + k * 32 + l));
            unsigned ad = xU + (unsigned)r * 256u + aswz(r, k >> 2) + (k & 3) * 4u;
            asm volatile("st.shared.f32 [%0], %1;" :: "r"(ad), "f"(v));
        }
    }
    __syncthreads();   // A, xm, tables, mbarriers all ready

    // prologue: warps 0..2 fill chunks 0..2 (no empty-wait on first use)
    if (w < 3) warp_fill(wpU, bU, mbU, w, lane);

    float acc[2][8][4];
#pragma unroll
    for (int i = 0; i < 2; ++i)
#pragma unroll
        for (int j = 0; j < 8; ++j)
#pragma unroll
            for (int q = 0; q < 4; ++q) acc[i][j][q] = 0.f;

    float* scr = g_scr + (size_t)blockIdx.x * 32768 + (size_t)w * 2048;
#define SCRP(i, j) (scr + ((size_t)((i) * 8 + (j)) * 32 + lane) * 4)

    const int lm = lane >> 3, lr = lane & 7;
    const unsigned bfb = (unsigned)(wc * 32 + lane) * 16u;

#pragma unroll 1
    for (int g = 0; g < 92; ++g) {
        // ---- round-robin producer: warp (g+3)&15 fills chunk g+3 ----
        if (g + 3 < 92 && w == ((g + 3) & 15)) {
            int gg = g + 3;
            MB_WAIT(mbU + 32u + (unsigned)(gg & 3) * 8u,
                    (unsigned)(((gg >> 2) & 1) ^ 1));
            warp_fill(wpU, bU, mbU, gg, lane);
        }
        // ---- consumer: wait data, compute ----
        const int sl = g & 3;
        MB_WAIT(mbU + (unsigned)sl * 8u, (unsigned)((g >> 2) & 1));

        unsigned rs, k4b;
        asm volatile("ld.shared.v2.u32 {%0, %1}, [%2];"
                     : "=r"(rs), "=r"(k4b) : "r"(axU + g * 8u));
        const unsigned abase = (rs == 256u) ? xU : aU;
        const unsigned bb = bU + (unsigned)sl * 16384u;
#pragma unroll
        for (int s = 0; s < 2; ++s) {
            uint32_t bf[8][2];
#pragma unroll
            for (int j4 = 0; j4 < 4; ++j4) {
                uint32_t v0, v1, v2, v3;
                asm volatile("ld.shared.v4.b32 {%0,%1,%2,%3}, [%4];"
                    : "=r"(v0), "=r"(v1), "=r"(v2), "=r"(v3)
                    : "r"(bb + (unsigned)(s * 4 + j4) * 2048u + bfb));
                bf[2 * j4][0] = v0; bf[2 * j4][1] = v1;
                bf[2 * j4 + 1][0] = v2; bf[2 * j4 + 1][1] = v3;
            }
            uint32_t af[2][4];
#pragma unroll
            for (int i = 0; i < 2; ++i) {
                int row = wr * 32 + i * 16 + (lm & 1) * 8 + lr;
                int k4  = (int)k4b + s * 2 + (lm >> 1);
                unsigned ad = abase + (unsigned)row * rs + aswz(row, k4);
                asm volatile("ldmatrix.sync.aligned.m8n8.x4.shared.b16 "
                             "{%0,%1,%2,%3}, [%4];"
                    : "=r"(af[i][0]), "=r"(af[i][1]),
                      "=r"(af[i][2]), "=r"(af[i][3])
                    : "r"(ad));
            }
#pragma unroll
            for (int i = 0; i < 2; ++i)
#pragma unroll
                for (int j = 0; j < 8; ++j)
                    asm volatile(
                        "mma.sync.aligned.m16n8k8.row.col.f32.tf32.tf32.f32 "
                        "{%0,%1,%2,%3}, {%4,%5,%6,%7}, {%8,%9}, {%0,%1,%2,%3};"
                        : "+f"(acc[i][j][0]), "+f"(acc[i][j][1]),
                          "+f"(acc[i][j][2]), "+f"(acc[i][j][3])
                        : "r"(af[i][0]), "r"(af[i][1]),
                          "r"(af[i][2]), "r"(af[i][3]),
                          "r"(bf[j][0]), "r"(bf[j][1]));
        }
        if (lane == 0) MB_ARRIVE(mbU + 32u + (unsigned)sl * 8u);

        // ---- inlined epilogues ----
        if (g == 19) {          // r = sigmoid(acc + bir) -> scratch; acc = 0
            const float* bb2 = bir + l * 256;
#pragma unroll
            for (int i = 0; i < 2; ++i)
#pragma unroll
                for (int j = 0; j < 8; ++j) {
                    int c0 = C0J;
                    float4 v;
                    v.x = sigm(acc[i][j][0] + __ldg(bb2 + c0));
                    v.y = sigm(acc[i][j][1] + __ldg(bb2 + c0 + 1));
                    v.z = sigm(acc[i][j][2] + __ldg(bb2 + c0));
                    v.w = sigm(acc[i][j][3] + __ldg(bb2 + c0 + 1));
                    *reinterpret_cast<float4*>(SCRP(i, j)) = v;
                    acc[i][j][0] = acc[i][j][1] = acc[i][j][2] = acc[i][j][3] = 0.f;
                }
        } else if (g == 35) {   // acc = r * (acc + bhn)
            const float* bb2 = bhn + l * 256;
#pragma unroll
            for (int i = 0; i < 2; ++i)
#pragma unroll
                for (int j = 0; j < 8; ++j) {
                    int c0 = C0J;
                    float4 rv = *reinterpret_cast<const float4*>(SCRP(i, j));
                    acc[i][j][0] = rv.x * (acc[i][j][0] + __ldg(bb2 + c0));
                    acc[i][j][1] = rv.y * (acc[i][j][1] + __ldg(bb2 + c0 + 1));
                    acc[i][j][2] = rv.z * (acc[i][j][2] + __ldg(bb2 + c0));
                    acc[i][j][3] = rv.w * (acc[i][j][3] + __ldg(bb2 + c0 + 1));
                }
        } else if (g == 39) {   // n = tanh(acc + bin) -> scratch; acc = 0
            const float* bb2 = bin_ + l * 256;
#pragma unroll
            for (int i = 0; i < 2; ++i)
#pragma unroll
                for (int j = 0; j < 8; ++j) {
                    int c0 = C0J;
                    float4 v;
                    v.x = ftanh(acc[i][j][0] + __ldg(bb2 + c0));
                    v.y = ftanh(acc[i][j][1] + __ldg(bb2 + c0 + 1));
                    v.z = ftanh(acc[i][j][2] + __ldg(bb2 + c0));
                    v.w = ftanh(acc[i][j][3] + __ldg(bb2 + c0 + 1));
                    *reinterpret_cast<float4*>(SCRP(i, j)) = v;
                    acc[i][j][0] = acc[i][j][1] = acc[i][j][2] = acc[i][j][3] = 0.f;
                }
        } else if (g == 59) {   // z = sigm(acc+biz); hnew = n + z*(h-n) -> A
            __syncthreads();    // all warps done READING h through chunk 59
            const float* bb2 = biz + l * 256;
#pragma unroll
            for (int i = 0; i < 2; ++i)
#pragma unroll
                for (int j = 0; j < 8; ++j) {
                    int c0 = C0J, r0 = R0I, r1 = r0 + 8;
                    float4 nv = *reinterpret_cast<const float4*>(SCRP(i, j));
                    float zz[4];
                    zz[0] = sigm(acc[i][j][0] + __ldg(bb2 + c0));
                    zz[1] = sigm(acc[i][j][1] + __ldg(bb2 + c0 + 1));
                    zz[2] = sigm(acc[i][j][2] + __ldg(bb2 + c0));
                    zz[3] = sigm(acc[i][j][3] + __ldg(bb2 + c0 + 1));
                    const int rr[4] = {r0, r0, r1, r1};
                    const int cc[4] = {c0, c0 + 1, c0, c0 + 1};
                    const float nn[4] = {nv.x, nv.y, nv.z, nv.w};
#pragma unroll
                    for (int q = 0; q < 4; ++q) {
                        unsigned ad = aU + (unsigned)rr[q] * 1024u
                                    + aswz(rr[q], cc[q] >> 2) + (cc[q] & 3) * 4u;
                        float h;
                        asm volatile("ld.shared.f32 %0, [%1];" : "=f"(h) : "r"(ad));
                        float hv = tf32r(nn[q] + zz[q] * (h - nn[q]));
                        asm volatile("st.shared.f32 [%0], %1;" :: "r"(ad), "f"(hv));
                        acc[i][j][q] = 0.f;
                    }
                }
            __syncthreads();    // hnew visible before anyone reads at g=60
        } else if (g == 75) {   // h1 = relu(acc + b1) -> A
            __syncthreads();
            const float* bb2 = b1 + l * 256;
#pragma unroll
            for (int i = 0; i < 2; ++i)
#pragma unroll
                for (int j = 0; j < 8; ++j) {
                    int c0 = C0J, r0 = R0I, r1 = r0 + 8;
                    const int rr[4] = {r0, r0, r1, r1};
                    const int cc[4] = {c0, c0 + 1, c0, c0 + 1};
#pragma unroll
                    for (int q = 0; q < 4; ++q) {
                        float hv = tf32r(fmaxf(acc[i][j][q] + __ldg(bb2 + cc[q]), 0.f));
                        unsigned ad = aU + (unsigned)rr[q] * 1024u
                                    + aswz(rr[q], cc[q] >> 2) + (cc[q] & 3) * 4u;
                        asm volatile("st.shared.f32 [%0], %1;" :: "r"(ad), "f"(hv));
                        acc[i][j][q] = 0.f;
                    }
                }
            __syncthreads();
        }
    }

    // ---- tail: h2 = relu(acc + b2) -> g_oT (8 lines/instr) + mu ----
    {
        const float* bb2 = b2 + l * 256;
        const float* wml = Wmu + l * 256;
        float* oT = g_oT + (size_t)l * 1048576 + (size_t)b0 * 256;
        float mup[2][2];
#pragma unroll
        for (int i = 0; i < 2; ++i) { mup[i][0] = 0.f; mup[i][1] = 0.f; }
#pragma unroll
        for (int i = 0; i < 2; ++i)
#pragma unroll
            for (int j = 0; j < 8; ++j) {
                int c0 = C0J, r0 = R0I, r1 = r0 + 8;
                float2 v0, v1;
                v0.x = fmaxf(acc[i][j][0] + __ldg(bb2 + c0), 0.f);
                v0.y = fmaxf(acc[i][j][1] + __ldg(bb2 + c0 + 1), 0.f);
                v1.x = fmaxf(acc[i][j][2] + __ldg(bb2 + c0), 0.f);
                v1.y = fmaxf(acc[i][j][3] + __ldg(bb2 + c0 + 1), 0.f);
                *reinterpret_cast<float2*>(oT + (size_t)r0 * 256 + c0) = v0;
                *reinterpret_cast<float2*>(oT + (size_t)r1 * 256 + c0) = v1;
                mup[i][0] += v0.x * __ldg(wml + c0) + v0.y * __ldg(wml + c0 + 1);
                mup[i][1] += v1.x * __ldg(wml + c0) + v1.y * __ldg(wml + c0 + 1);
            }
#pragma unroll
        for (int i = 0; i < 2; ++i)
#pragma unroll
            for (int hq = 0; hq < 2; ++hq) {
                float v = mup[i][hq];
                v += __shfl_xor_sync(0xffffffffu, v, 1);
                v += __shfl_xor_sync(0xffffffffu, v, 2);
                if ((lane & 3) == 0)
                    atomicAdd(&mu_s[wr * 32 + i * 16 + (lane >> 2) + hq * 8], v);
            }
    }
    __syncthreads();
    if (tid < 128) {
        out[BHL + (size_t)(b0 + tid) * 32 + l] = mu_s[tid] + __ldg(bmu + l);
        out[BHL + BLc + (size_t)(b0 + tid) * 32 + l] =
            fmaxf(__ldg(log_var + l), -3.0f);
    }
}

extern "C" void kernel_launch(void* const* d_in, const int* in_sizes, int n_in,
                              void* d_out, int out_size) {
    const float* hidden  = (const float*)d_in[0];
    const float* x       = (const float*)d_in[1];
    const float* mask    = (const float*)d_in[2];
    const float* Wir     = (const float*)d_in[3];
    const float* bir     = (const float*)d_in[4];
    const float* Wiz     = (const float*)d_in[5];
    const float* biz     = (const float*)d_in[6];
    const float* Win     = (const float*)d_in[7];
    const float* bin_    = (const float*)d_in[8];
    const float* Whr     = (const float*)d_in[9];
    const float* Whz     = (const float*)d_in[10];
    const float* Whn     = (const float*)d_in[11];
    const float* bhn     = (const float*)d_in[12];
    const float* W1      = (const float*)d_in[13];
    const float* b1      = (const float*)d_in[14];
    const float* W2      = (const float*)d_in[15];
    const float* b2      = (const float*)d_in[16];
    const float* Wmu     = (const float*)d_in[17];
    const float* bmu     = (const float*)d_in[18];
    const float* log_var = (const float*)d_in[19];
    float* out = (float*)d_out;

    cudaFuncSetAttribute(prnn_mma, cudaFuncAttributeMaxDynamicSharedMemorySize,
                         SMEM_BYTES);
    prep<<<7040, 256>>>(Whr, Whn, Whz, W1, W2, Wir, Win, Wiz, hidden);
    prnn_mma<<<1024, 512, SMEM_BYTES>>>(x, mask, bir, biz, bin_, bhn,
                                        b1, b2, Wmu, bmu, log_var, out);
    otrans<<<4096, 256>>>(out);
}